// round 2
// baseline (speedup 1.0000x reference)
#include <cuda_runtime.h>
#include <cstdint>
#include <cstddef>

#define NTOK 2048    // B*L tokens
#define DM   1024
#define DI   2048
#define DS   16
#define LSEQ 1024

// ------------------------- scratch (static device memory) -------------------------
__device__ float g_xn[NTOK * DM];        // rmsnormed x
__device__ float g_proj[NTOK * 2 * DI];  // [x_branch | gate]
__device__ float g_xc[NTOK * DI];        // conv+silu output
__device__ float g_dt[NTOK * DI];        // dt after softplus+softclamp
__device__ float g_Bp[NTOK * DS];
__device__ float g_Cp[NTOK * DS];
__device__ float g_xssm[NTOK * DI];
__device__ float g_gated[NTOK * DI];

// ------------------------- rmsnorm -------------------------
__global__ void rmsnorm_kernel(const float* __restrict__ x, const float* __restrict__ w)
{
    __shared__ float red[8];
    int token = blockIdx.x;
    int tid = threadIdx.x;  // 256
    const float4* xr = reinterpret_cast<const float4*>(x + (size_t)token * DM);
    float4 v = xr[tid];
    float ss = v.x * v.x + v.y * v.y + v.z * v.z + v.w * v.w;
#pragma unroll
    for (int o = 16; o; o >>= 1) ss += __shfl_xor_sync(0xffffffffu, ss, o);
    if ((tid & 31) == 0) red[tid >> 5] = ss;
    __syncthreads();
    float tot = 0.f;
#pragma unroll
    for (int i = 0; i < 8; i++) tot += red[i];
    float r = rsqrtf(tot * (1.f / (float)DM) + 1e-6f);
    const float4* wr = reinterpret_cast<const float4*>(w);
    float4 wv = wr[tid];
    float4 o4;
    o4.x = v.x * r * wv.x;
    o4.y = v.y * r * wv.y;
    o4.z = v.z * r * wv.z;
    o4.w = v.w * r * wv.w;
    reinterpret_cast<float4*>(g_xn + (size_t)token * DM)[tid] = o4;
}

// ------------------------- SGEMM (NT: C[M,N] = A[M,K] * B[N,K]^T) -------------------------
// MODE 0: plain. MODE 1: dt epilogue (bias + softplus + softclamp). MODE 2: residual epilogue.
template <int MODE>
__global__ void __launch_bounds__(256) sgemm_nt(
    const float* __restrict__ Ag, const float* __restrict__ Bg, float* __restrict__ Cg,
    int M, int N, int K,
    const float* __restrict__ bias, const float* __restrict__ resid,
    const float* __restrict__ scale_ptr)
{
    __shared__ float As[16][128];
    __shared__ float Bs[16][128];
    const int tid = threadIdx.x;
    const int bm = blockIdx.y * 128;
    const int bn = blockIdx.x * 128;

    float acc[8][8];
#pragma unroll
    for (int i = 0; i < 8; i++)
#pragma unroll
        for (int j = 0; j < 8; j++) acc[i][j] = 0.f;

    const int tr = (tid >> 4) << 3;  // 0..120
    const int tc = (tid & 15) << 3;  // 0..120

    const float* Abase = Ag + (size_t)bm * K;
    const float* Bbase = Bg + (size_t)bn * K;

    for (int k0 = 0; k0 < K; k0 += 16) {
#pragma unroll
        for (int i = 0; i < 2; i++) {
            int e = tid * 2 + i;
            int row = e >> 2;
            int c4 = (e & 3) << 2;
            float4 av = *reinterpret_cast<const float4*>(Abase + (size_t)row * K + k0 + c4);
            As[c4 + 0][row] = av.x;
            As[c4 + 1][row] = av.y;
            As[c4 + 2][row] = av.z;
            As[c4 + 3][row] = av.w;
            float4 bv = *reinterpret_cast<const float4*>(Bbase + (size_t)row * K + k0 + c4);
            Bs[c4 + 0][row] = bv.x;
            Bs[c4 + 1][row] = bv.y;
            Bs[c4 + 2][row] = bv.z;
            Bs[c4 + 3][row] = bv.w;
        }
        __syncthreads();
#pragma unroll
        for (int k = 0; k < 16; k++) {
            float a[8], bb[8];
            *reinterpret_cast<float4*>(&a[0]) = *reinterpret_cast<const float4*>(&As[k][tr]);
            *reinterpret_cast<float4*>(&a[4]) = *reinterpret_cast<const float4*>(&As[k][tr + 4]);
            *reinterpret_cast<float4*>(&bb[0]) = *reinterpret_cast<const float4*>(&Bs[k][tc]);
            *reinterpret_cast<float4*>(&bb[4]) = *reinterpret_cast<const float4*>(&Bs[k][tc + 4]);
#pragma unroll
            for (int i = 0; i < 8; i++)
#pragma unroll
                for (int j = 0; j < 8; j++) acc[i][j] = fmaf(a[i], bb[j], acc[i][j]);
        }
        __syncthreads();
    }

    float scale = 0.f;
    if (MODE == 2) scale = 0.5f / (1.f + expf(-scale_ptr[0]));

#pragma unroll
    for (int i = 0; i < 8; i++) {
        size_t row = (size_t)(bm + tr + i);
#pragma unroll
        for (int j = 0; j < 8; j++) {
            int col = bn + tc + j;
            float v = acc[i][j];
            if (MODE == 1) {
                float pre = v + bias[col];
                // softplus (stable) then soft_clamp(.., 0.001, 0.1, 0.5)
                float sp = fmaxf(pre, 0.f) + log1pf(expf(-fabsf(pre)));
                float arg = (sp - 0.0505f) * (0.5f / (0.0495f + 1e-8f));
                v = tanhf(arg) * 0.099f + 0.0505f;
            } else if (MODE == 2) {
                v = resid[row * (size_t)N + col] + scale * v;
            }
            Cg[row * (size_t)N + col] = v;
        }
    }
}

// ------------------------- depthwise causal conv4 + SiLU -------------------------
__global__ void conv_silu_kernel(const float* __restrict__ conv_w, const float* __restrict__ conv_b)
{
    int token = blockIdx.x;
    int t = token & (LSEQ - 1);
    for (int d = threadIdx.x; d < DI; d += blockDim.x) {
        float4 w = *reinterpret_cast<const float4*>(conv_w + (size_t)d * 4);
        float acc = conv_b[d];
        const float* base = g_proj + (size_t)token * (2 * DI) + d;
        if (t >= 3) acc = fmaf(w.x, base[-3 * 2 * DI], acc);
        if (t >= 2) acc = fmaf(w.y, base[-2 * 2 * DI], acc);
        if (t >= 1) acc = fmaf(w.z, base[-1 * 2 * DI], acc);
        acc = fmaf(w.w, base[0], acc);
        float s = 1.f / (1.f + expf(-acc));
        g_xc[(size_t)token * DI + d] = acc * s;
    }
}

// ------------------------- Bp / Cp projections (N=16 each) -------------------------
// 4 tokens per block, 256 threads. Warp w handles outputs {w, w+8, w+16, w+24};
// outputs 0..15 -> W_B, 16..31 -> W_C.
__global__ void __launch_bounds__(256) bpcp_kernel(const float* __restrict__ W_B, const float* __restrict__ W_C)
{
    __shared__ float sx[4][DI];
    int tok0 = blockIdx.x * 4;
    int tid = threadIdx.x;
    for (int i = tid; i < 4 * DI; i += 256) {
        int r = i >> 11;
        int dd = i & (DI - 1);
        sx[r][dd] = g_xc[(size_t)(tok0 + r) * DI + dd];
    }
    __syncthreads();
    int wid = tid >> 5, lane = tid & 31;
#pragma unroll
    for (int oo = 0; oo < 4; oo++) {
        int o = wid + oo * 8;
        const float* Wr = (o < 16) ? (W_B + (size_t)o * DI) : (W_C + (size_t)(o - 16) * DI);
        float a0 = 0.f, a1 = 0.f, a2 = 0.f, a3 = 0.f;
        for (int dd = lane; dd < DI; dd += 32) {
            float w = Wr[dd];
            a0 = fmaf(w, sx[0][dd], a0);
            a1 = fmaf(w, sx[1][dd], a1);
            a2 = fmaf(w, sx[2][dd], a2);
            a3 = fmaf(w, sx[3][dd], a3);
        }
#pragma unroll
        for (int off = 16; off; off >>= 1) {
            a0 += __shfl_xor_sync(0xffffffffu, a0, off);
            a1 += __shfl_xor_sync(0xffffffffu, a1, off);
            a2 += __shfl_xor_sync(0xffffffffu, a2, off);
            a3 += __shfl_xor_sync(0xffffffffu, a3, off);
        }
        if (lane == 0) {
            float* outp = (o < 16) ? g_Bp : g_Cp;
            int oc = (o < 16) ? o : (o - 16);
            outp[(tok0 + 0) * DS + oc] = a0;
            outp[(tok0 + 1) * DS + oc] = a1;
            outp[(tok0 + 2) * DS + oc] = a2;
            outp[(tok0 + 3) * DS + oc] = a3;
        }
    }
}

// ------------------------- selective scan (cluster of 8 CTAs per batch) -------------------------
template <int NS>
__device__ __forceinline__ void scan_chunk(
    int t0, int cidx, int tid,
    float* h, const float* A, float Dv,
    const float* dtb, const float* xcb, float* yb,
    const float* Bpb, const float* Cpb,
    float (*sB)[16], float (*sC)[16],
    float* warp_part, float* slot, float* s_fac, uint32_t slot_u32)
{
    __syncthreads();  // protect smem reuse across chunks
    for (int i = tid; i < NS * 16; i += 256) {
        int s = i >> 4, n = i & 15;
        sB[s][n] = Bpb[(size_t)(t0 + s) * DS + n];
        sC[s][n] = Cpb[(size_t)(t0 + s) * DS + n];
    }
    float dtv[NS], xcv[NS];
#pragma unroll
    for (int s = 0; s < NS; s++) {
        dtv[s] = dtb[(size_t)(t0 + s) * DI];
        xcv[s] = xcb[(size_t)(t0 + s) * DI];
    }
    __syncthreads();

#pragma unroll
    for (int s = 0; s < NS; s++) {
        float dt_ = dtv[s], xc_ = xcv[s];
        float dtx = dt_ * xc_;
#pragma unroll
        for (int n = 0; n < 16; n++) {
            float z = dt_ * A[n];
            // e = 16*tanh(z/16); polynomial exact for |z| < 1 (fallback for safety)
            float z2 = z * z;
            float e = z + z * z2 * fmaf(z2, 2.0345052e-6f, -1.3020833e-3f);
            if (fabsf(z) >= 1.0f) e = 16.f * tanhf(z * 0.0625f);
            float dA = __expf(e);
            h[n] = fmaf(h[n], dA, dtx * sB[s][n]);
        }
        if (s == 0) {  // t0 % 10 == 0 always: global norm event
            float ss = 0.f;
#pragma unroll
            for (int n = 0; n < 16; n++) ss = fmaf(h[n], h[n], ss);
#pragma unroll
            for (int o = 16; o; o >>= 1) ss += __shfl_xor_sync(0xffffffffu, ss, o);
            if ((tid & 31) == 0) warp_part[tid >> 5] = ss;
            __syncthreads();
            int par = cidx & 1;
            if (tid == 0) {
                float blk = 0.f;
#pragma unroll
                for (int w = 0; w < 8; w++) blk += warp_part[w];
                slot[par] = blk;
            }
            asm volatile("barrier.cluster.arrive.aligned;" ::: "memory");
            asm volatile("barrier.cluster.wait.aligned;" ::: "memory");
            if (tid == 0) {
                float tot = 0.f;
#pragma unroll
                for (int r = 0; r < 8; r++) {
                    uint32_t rem;
                    asm volatile("mapa.shared::cluster.u32 %0, %1, %2;"
                                 : "=r"(rem)
                                 : "r"(slot_u32 + (uint32_t)(par * 4)), "r"(r));
                    float v;
                    asm volatile("ld.shared::cluster.f32 %0, [%1];" : "=f"(v) : "r"(rem));
                    tot += v;
                }
                float nrm = sqrtf(tot);
                *s_fac = fminf(20.f / (nrm + 1e-8f), 1.f);
            }
            __syncthreads();
            float fac = *s_fac;
#pragma unroll
            for (int n = 0; n < 16; n++) h[n] *= fac;
        }
        float y = Dv * xc_;
#pragma unroll
        for (int n = 0; n < 16; n++) y = fmaf(h[n], sC[s][n], y);
        yb[(size_t)(t0 + s) * DI] = y;
    }
}

__global__ void __cluster_dims__(8, 1, 1) __launch_bounds__(256)
scan_kernel(const float* __restrict__ A_log, const float* __restrict__ Dp)
{
    __shared__ float sB[10][16], sC[10][16];
    __shared__ float warp_part[8];
    __shared__ float slot[2];
    __shared__ float s_fac;

    int tid = threadIdx.x;
    int b = blockIdx.x >> 3;
    int rk = blockIdx.x & 7;
    int d = rk * 256 + tid;

    float A[16], h[16];
#pragma unroll
    for (int n = 0; n < 16; n++) {
        float al = A_log[(size_t)d * 16 + n];
        A[n] = -expf(10.f * tanhf(0.1f * al));  // -exp(soft_clamp(A_log,-5,5,0.5))
        h[n] = 0.f;
    }
    float Dv = Dp[d];

    const float* dtb = g_dt + (size_t)b * LSEQ * DI + d;
    const float* xcb = g_xc + (size_t)b * LSEQ * DI + d;
    float* yb = g_xssm + (size_t)b * LSEQ * DI + d;
    const float* Bpb = g_Bp + (size_t)b * LSEQ * DS;
    const float* Cpb = g_Cp + (size_t)b * LSEQ * DS;

    uint32_t slot_u32 = (uint32_t)__cvta_generic_to_shared(slot);

    for (int c = 0; c < 102; c++)
        scan_chunk<10>(c * 10, c, tid, h, A, Dv, dtb, xcb, yb, Bpb, Cpb,
                       sB, sC, warp_part, slot, &s_fac, slot_u32);
    scan_chunk<4>(1020, 102, tid, h, A, Dv, dtb, xcb, yb, Bpb, Cpb,
                  sB, sC, warp_part, slot, &s_fac, slot_u32);
}

// ------------------------- gate (x_ssm * silu(gate)) -------------------------
__global__ void gate_kernel()
{
    size_t i = (size_t)blockIdx.x * blockDim.x + threadIdx.x;
    int token = (int)(i >> 11);
    int dd = (int)(i & (DI - 1));
    float g = g_proj[(size_t)token * (2 * DI) + DI + dd];
    float sg = g / (1.f + expf(-g));
    g_gated[i] = g_xssm[i] * sg;
}

// ------------------------- launch -------------------------
extern "C" void kernel_launch(void* const* d_in, const int* in_sizes, int n_in,
                              void* d_out, int out_size)
{
    const float* x       = (const float*)d_in[0];
    const float* norm_w  = (const float*)d_in[1];
    const float* W_in    = (const float*)d_in[2];
    const float* conv_w  = (const float*)d_in[3];
    const float* conv_b  = (const float*)d_in[4];
    const float* W_dt    = (const float*)d_in[5];
    const float* b_dt    = (const float*)d_in[6];
    const float* W_B     = (const float*)d_in[7];
    const float* W_C     = (const float*)d_in[8];
    const float* A_log   = (const float*)d_in[9];
    const float* D_param = (const float*)d_in[10];
    const float* W_out   = (const float*)d_in[11];
    const float* r_scale = (const float*)d_in[12];
    float* out = (float*)d_out;

    void *p_xn, *p_proj, *p_xc, *p_dt, *p_gated;
    cudaGetSymbolAddress(&p_xn, g_xn);
    cudaGetSymbolAddress(&p_proj, g_proj);
    cudaGetSymbolAddress(&p_xc, g_xc);
    cudaGetSymbolAddress(&p_dt, g_dt);
    cudaGetSymbolAddress(&p_gated, g_gated);

    // 1. RMSNorm
    rmsnorm_kernel<<<NTOK, 256>>>(x, norm_w);
    // 2. in-projection: proj[2048,4096] = xn[2048,1024] @ W_in^T
    sgemm_nt<0><<<dim3(4096 / 128, NTOK / 128), 256>>>(
        (const float*)p_xn, W_in, (float*)p_proj, NTOK, 4096, 1024, nullptr, nullptr, nullptr);
    // 3. depthwise conv + silu
    conv_silu_kernel<<<NTOK, 256>>>(conv_w, conv_b);
    // 4. dt = softclamp(softplus(xc @ W_dt^T + b_dt))
    sgemm_nt<1><<<dim3(DI / 128, NTOK / 128), 256>>>(
        (const float*)p_xc, W_dt, (float*)p_dt, NTOK, DI, DI, b_dt, nullptr, nullptr);
    // 5. Bp / Cp
    bpcp_kernel<<<NTOK / 4, 256>>>(W_B, W_C);
    // 6. selective scan (2 clusters of 8 CTAs)
    scan_kernel<<<16, 256>>>(A_log, D_param);
    // 7. gating
    gate_kernel<<<(NTOK * DI) / 256, 256>>>();
    // 8. out-projection + residual
    sgemm_nt<2><<<dim3(DM / 128, NTOK / 128), 256>>>(
        (const float*)p_gated, W_out, out, NTOK, DM, DI, nullptr, x, r_scale);
}

// round 4
// speedup vs baseline: 1.9098x; 1.9098x over previous
#include <cuda_runtime.h>
#include <cuda_bf16.h>
#include <cstdint>
#include <cstddef>

#define NTOK 2048
#define DM   1024
#define DI   2048
#define DS   16
#define LSEQ 1024

typedef unsigned long long ull;

// ------------------------- scratch -------------------------
__device__ float g_proj[NTOK * 2 * DI];
__device__ float g_xc[NTOK * DI];
__device__ float g_dt[NTOK * DI];
__device__ float g_Bp[NTOK * DS];
__device__ float g_Cp[NTOK * DS];
__device__ float g_xssm[NTOK * DI];

__device__ __nv_bfloat16 g_xn_h[NTOK * DM],    g_xn_l[NTOK * DM];
__device__ __nv_bfloat16 g_xc_h[NTOK * DI],    g_xc_l[NTOK * DI];
__device__ __nv_bfloat16 g_gate_h[NTOK * DI],  g_gate_l[NTOK * DI];
__device__ __nv_bfloat16 g_Win_h[2 * DI * DM], g_Win_l[2 * DI * DM];
__device__ __nv_bfloat16 g_Wdt_h[DI * DI],     g_Wdt_l[DI * DI];
__device__ __nv_bfloat16 g_Wout_h[DM * DI],    g_Wout_l[DM * DI];

// ------------------------- PTX helpers -------------------------
__device__ __forceinline__ uint32_t cvta_s(const void* p) {
    uint32_t a;
    asm("{.reg .u64 t; cvta.to.shared.u64 t, %1; cvt.u32.u64 %0, t;}" : "=r"(a) : "l"(p));
    return a;
}
__device__ __forceinline__ void cp_async16(uint32_t saddr, const void* gaddr) {
    asm volatile("cp.async.cg.shared.global [%0], [%1], 16;" :: "r"(saddr), "l"(gaddr));
}
#define CP_COMMIT() asm volatile("cp.async.commit_group;" ::: "memory")
#define CP_WAIT(n)  asm volatile("cp.async.wait_group %0;" :: "n"(n) : "memory")

__device__ __forceinline__ void ldsm4(uint32_t* r, uint32_t addr) {
    asm volatile("ldmatrix.sync.aligned.m8n8.x4.shared.b16 {%0,%1,%2,%3}, [%4];"
                 : "=r"(r[0]), "=r"(r[1]), "=r"(r[2]), "=r"(r[3]) : "r"(addr));
}
__device__ __forceinline__ void mma16816(float* c, const uint32_t* a, const uint32_t* b) {
    asm volatile("mma.sync.aligned.m16n8k16.row.col.f32.bf16.bf16.f32 "
                 "{%0,%1,%2,%3},{%4,%5,%6,%7},{%8,%9},{%0,%1,%2,%3};"
                 : "+f"(c[0]), "+f"(c[1]), "+f"(c[2]), "+f"(c[3])
                 : "r"(a[0]), "r"(a[1]), "r"(a[2]), "r"(a[3]), "r"(b[0]), "r"(b[1]));
}

__device__ __forceinline__ ull pk2(float lo, float hi) {
    ull r; asm("mov.b64 %0,{%1,%2};" : "=l"(r) : "f"(lo), "f"(hi)); return r;
}
__device__ __forceinline__ float2 upk2(ull v) {
    float2 f; asm("mov.b64 {%0,%1},%2;" : "=f"(f.x), "=f"(f.y) : "l"(v)); return f;
}
__device__ __forceinline__ ull fma2_(ull a, ull b, ull c) {
    ull d; asm("fma.rn.f32x2 %0,%1,%2,%3;" : "=l"(d) : "l"(a), "l"(b), "l"(c)); return d;
}
__device__ __forceinline__ ull mul2_(ull a, ull b) {
    ull d; asm("mul.rn.f32x2 %0,%1,%2;" : "=l"(d) : "l"(a), "l"(b)); return d;
}
__device__ __forceinline__ float ex2_(float x) {
    float y; asm("ex2.approx.f32 %0,%1;" : "=f"(y) : "f"(x)); return y;
}

__device__ __forceinline__ void split_bf16(float x, __nv_bfloat16& h, __nv_bfloat16& l) {
    h = __float2bfloat16_rn(x);
    l = __float2bfloat16_rn(x - __bfloat162float(h));
}

// ------------------------- fp32 -> bf16 hi/lo conversion -------------------------
__global__ void cvt_hl_kernel(const float* __restrict__ src,
                              __nv_bfloat16* __restrict__ h, __nv_bfloat16* __restrict__ l,
                              int n4)
{
    int i = blockIdx.x * blockDim.x + threadIdx.x;
    if (i >= n4) return;
    float4 v = reinterpret_cast<const float4*>(src)[i];
    __nv_bfloat162 h0, h1, l0, l1;
    split_bf16(v.x, h0.x, l0.x); split_bf16(v.y, h0.y, l0.y);
    split_bf16(v.z, h1.x, l1.x); split_bf16(v.w, h1.y, l1.y);
    reinterpret_cast<__nv_bfloat162*>(h)[2 * i]     = h0;
    reinterpret_cast<__nv_bfloat162*>(h)[2 * i + 1] = h1;
    reinterpret_cast<__nv_bfloat162*>(l)[2 * i]     = l0;
    reinterpret_cast<__nv_bfloat162*>(l)[2 * i + 1] = l1;
}

// ------------------------- rmsnorm (-> bf16 hi/lo) -------------------------
__global__ void rmsnorm_kernel(const float* __restrict__ x, const float* __restrict__ w)
{
    __shared__ float red[8];
    int token = blockIdx.x;
    int tid = threadIdx.x;  // 256
    float4 v = reinterpret_cast<const float4*>(x + (size_t)token * DM)[tid];
    float ss = v.x * v.x + v.y * v.y + v.z * v.z + v.w * v.w;
#pragma unroll
    for (int o = 16; o; o >>= 1) ss += __shfl_xor_sync(0xffffffffu, ss, o);
    if ((tid & 31) == 0) red[tid >> 5] = ss;
    __syncthreads();
    float tot = 0.f;
#pragma unroll
    for (int i = 0; i < 8; i++) tot += red[i];
    float r = rsqrtf(tot * (1.f / (float)DM) + 1e-6f);
    float4 wv = reinterpret_cast<const float4*>(w)[tid];
    float o0 = v.x * r * wv.x, o1 = v.y * r * wv.y;
    float o2 = v.z * r * wv.z, o3 = v.w * r * wv.w;
    __nv_bfloat162 h0, h1, l0, l1;
    split_bf16(o0, h0.x, l0.x); split_bf16(o1, h0.y, l0.y);
    split_bf16(o2, h1.x, l1.x); split_bf16(o3, h1.y, l1.y);
    size_t base = (size_t)token * (DM / 2) + tid * 2;
    reinterpret_cast<__nv_bfloat162*>(g_xn_h)[base]     = h0;
    reinterpret_cast<__nv_bfloat162*>(g_xn_h)[base + 1] = h1;
    reinterpret_cast<__nv_bfloat162*>(g_xn_l)[base]     = l0;
    reinterpret_cast<__nv_bfloat162*>(g_xn_l)[base + 1] = l1;
}

// ------------------------- HMMA bf16x3 GEMM (NT) -------------------------
// C[M,N] = A[M,K]*B[N,K]^T with A,B as bf16 hi/lo pairs, fp32 accumulation.
// CTA tile 128x128, 8 warps of 64x32, K-step 16, cp.async double buffer.
// smem row padded to 24 bf16 (48B) for conflict-free ldmatrix.
#define SROW 24
#define STILE (128 * SROW)   // elements per tile (hi or lo, A or B)

template <int MODE>
__global__ void __launch_bounds__(256, 1) gemm_hmma(
    const __nv_bfloat16* __restrict__ Ah, const __nv_bfloat16* __restrict__ Al,
    const __nv_bfloat16* __restrict__ Bh, const __nv_bfloat16* __restrict__ Bl,
    float* __restrict__ Cg, int N, int K,
    const float* __restrict__ bias, const float* __restrict__ resid,
    const float* __restrict__ scale_ptr)
{
    __shared__ __nv_bfloat16 sm[2][4][STILE];   // 2 buf x {Ah,Al,Bh,Bl} x 6144B = 48KB

    const int tid = threadIdx.x, wid = tid >> 5, lane = tid & 31;
    const int bm = blockIdx.y * 128, bn = blockIdx.x * 128;
    const int warp_m = wid >> 2, warp_n = wid & 3;

    float acc[4][4][4];
#pragma unroll
    for (int i = 0; i < 4; i++)
#pragma unroll
        for (int j = 0; j < 4; j++)
#pragma unroll
            for (int q = 0; q < 4; q++) acc[i][j][q] = 0.f;

    const __nv_bfloat16* srcs[4] = {
        Ah + (size_t)bm * K, Al + (size_t)bm * K,
        Bh + (size_t)bn * K, Bl + (size_t)bn * K };

    const int row = tid >> 1, half = tid & 1;
    const uint32_t smb = cvta_s(sm);
    const uint32_t dst_off = (uint32_t)(row * SROW + half * 8) * 2;

    // ldmatrix per-lane byte offsets (within one tile)
    uint32_t a_off[4], b_off[2];
#pragma unroll
    for (int i = 0; i < 4; i++) {
        int r = warp_m * 64 + i * 16 + (lane & 15);
        a_off[i] = (uint32_t)(r * SROW + (lane >> 4) * 8) * 2;
    }
#pragma unroll
    for (int g = 0; g < 2; g++) {
        int n = warp_n * 32 + g * 16 + ((lane >> 4) & 1) * 8 + (lane & 7);
        b_off[g] = (uint32_t)(n * SROW + ((lane >> 3) & 1) * 8) * 2;
    }

    const int nst = K >> 4;
    // preload k-step 0 into buf 0
#pragma unroll
    for (int t = 0; t < 4; t++)
        cp_async16(smb + (uint32_t)(t * STILE) * 2 + dst_off,
                   srcs[t] + (size_t)row * K + half * 8);
    CP_COMMIT();

    for (int c = 0; c < nst; c++) {
        if (c + 1 < nst) {
            uint32_t bufb = smb + (uint32_t)(((c + 1) & 1) * 4 * STILE) * 2;
            const size_t goff = (size_t)row * K + (c + 1) * 16 + half * 8;
#pragma unroll
            for (int t = 0; t < 4; t++)
                cp_async16(bufb + (uint32_t)(t * STILE) * 2 + dst_off, srcs[t] + goff);
            CP_COMMIT();
            CP_WAIT(1);
        } else {
            CP_WAIT(0);
        }
        __syncthreads();

        const uint32_t bb = smb + (uint32_t)((c & 1) * 4 * STILE) * 2;
        uint32_t ah[4][4], al[4][4], bh[4][2], bl[4][2];
#pragma unroll
        for (int i = 0; i < 4; i++) {
            ldsm4(ah[i], bb + a_off[i]);
            ldsm4(al[i], bb + (uint32_t)STILE * 2 + a_off[i]);
        }
#pragma unroll
        for (int g = 0; g < 2; g++) {
            uint32_t r[4];
            ldsm4(r, bb + (uint32_t)(2 * STILE) * 2 + b_off[g]);
            bh[2 * g][0] = r[0]; bh[2 * g][1] = r[1];
            bh[2 * g + 1][0] = r[2]; bh[2 * g + 1][1] = r[3];
            ldsm4(r, bb + (uint32_t)(3 * STILE) * 2 + b_off[g]);
            bl[2 * g][0] = r[0]; bl[2 * g][1] = r[1];
            bl[2 * g + 1][0] = r[2]; bl[2 * g + 1][1] = r[3];
        }
#pragma unroll
        for (int i = 0; i < 4; i++)
#pragma unroll
            for (int j = 0; j < 4; j++) {
                mma16816(acc[i][j], ah[i], bh[j]);
                mma16816(acc[i][j], ah[i], bl[j]);
                mma16816(acc[i][j], al[i], bh[j]);
            }
        __syncthreads();
    }

    float scale = 0.f;
    if (MODE == 2) scale = 0.5f / (1.f + expf(-scale_ptr[0]));

#pragma unroll
    for (int i = 0; i < 4; i++)
#pragma unroll
        for (int j = 0; j < 4; j++) {
            int rr = bm + warp_m * 64 + i * 16 + (lane >> 2);
            int cc = bn + warp_n * 32 + j * 8 + (lane & 3) * 2;
#pragma unroll
            for (int hrow = 0; hrow < 2; hrow++) {
                size_t r = (size_t)(rr + hrow * 8);
                float v0 = acc[i][j][hrow * 2], v1 = acc[i][j][hrow * 2 + 1];
                if (MODE == 1) {
                    float p0 = v0 + bias[cc], p1 = v1 + bias[cc + 1];
                    float s0 = fmaxf(p0, 0.f) + log1pf(expf(-fabsf(p0)));
                    float s1 = fmaxf(p1, 0.f) + log1pf(expf(-fabsf(p1)));
                    v0 = tanhf((s0 - 0.0505f) * (0.5f / (0.0495f + 1e-8f))) * 0.099f + 0.0505f;
                    v1 = tanhf((s1 - 0.0505f) * (0.5f / (0.0495f + 1e-8f))) * 0.099f + 0.0505f;
                } else if (MODE == 2) {
                    v0 = resid[r * N + cc] + scale * v0;
                    v1 = resid[r * N + cc + 1] + scale * v1;
                }
                *reinterpret_cast<float2*>(Cg + r * N + cc) = make_float2(v0, v1);
            }
        }
}

// ------------------------- conv4 + SiLU (-> fp32 + bf16 hi/lo) -------------------------
__global__ void conv_silu_kernel(const float* __restrict__ conv_w, const float* __restrict__ conv_b)
{
    int token = blockIdx.x;
    int t = token & (LSEQ - 1);
    for (int d = threadIdx.x; d < DI; d += blockDim.x) {
        float4 w = *reinterpret_cast<const float4*>(conv_w + (size_t)d * 4);
        float acc = conv_b[d];
        const float* base = g_proj + (size_t)token * (2 * DI) + d;
        if (t >= 3) acc = fmaf(w.x, base[-3 * 2 * DI], acc);
        if (t >= 2) acc = fmaf(w.y, base[-2 * 2 * DI], acc);
        if (t >= 1) acc = fmaf(w.z, base[-1 * 2 * DI], acc);
        acc = fmaf(w.w, base[0], acc);
        float s = 1.f / (1.f + expf(-acc));
        float val = acc * s;
        size_t idx = (size_t)token * DI + d;
        g_xc[idx] = val;
        __nv_bfloat16 h, l;
        split_bf16(val, h, l);
        g_xc_h[idx] = h;
        g_xc_l[idx] = l;
    }
}

// ------------------------- Bp / Cp projections -------------------------
__global__ void __launch_bounds__(256) bpcp_kernel(const float* __restrict__ W_B,
                                                   const float* __restrict__ W_C)
{
    __shared__ float sx[4][DI];
    int tok0 = blockIdx.x * 4;
    int tid = threadIdx.x;
    for (int i = tid; i < 4 * DI; i += 256) {
        int r = i >> 11, dd = i & (DI - 1);
        sx[r][dd] = g_xc[(size_t)(tok0 + r) * DI + dd];
    }
    __syncthreads();
    int wid = tid >> 5, lane = tid & 31;
#pragma unroll
    for (int oo = 0; oo < 4; oo++) {
        int o = wid + oo * 8;
        const float* Wr = (o < 16) ? (W_B + (size_t)o * DI) : (W_C + (size_t)(o - 16) * DI);
        float a0 = 0.f, a1 = 0.f, a2 = 0.f, a3 = 0.f;
        for (int dd = lane; dd < DI; dd += 32) {
            float w = Wr[dd];
            a0 = fmaf(w, sx[0][dd], a0);
            a1 = fmaf(w, sx[1][dd], a1);
            a2 = fmaf(w, sx[2][dd], a2);
            a3 = fmaf(w, sx[3][dd], a3);
        }
#pragma unroll
        for (int off = 16; off; off >>= 1) {
            a0 += __shfl_xor_sync(0xffffffffu, a0, off);
            a1 += __shfl_xor_sync(0xffffffffu, a1, off);
            a2 += __shfl_xor_sync(0xffffffffu, a2, off);
            a3 += __shfl_xor_sync(0xffffffffu, a3, off);
        }
        if (lane == 0) {
            float* outp = (o < 16) ? g_Bp : g_Cp;
            int oc = (o < 16) ? o : (o - 16);
            outp[(tok0 + 0) * DS + oc] = a0;
            outp[(tok0 + 1) * DS + oc] = a1;
            outp[(tok0 + 2) * DS + oc] = a2;
            outp[(tok0 + 3) * DS + oc] = a3;
        }
    }
}

// ------------------------- selective scan -------------------------
template <int NS>
__device__ __forceinline__ void scan_chunk(
    int t0, int cidx, int tid,
    ull* h2, const ull* AL2, float Dv,
    const float* dtb, const float* xcb, float* yb,
    const float* Bpb, const float* Cpb,
    float (*sB)[16], float (*sC)[16],
    float* warp_part, float* slot, float* s_fac, uint32_t slot_u32)
{
    const ull negc2 = pk2(-6.2559045e-4f, -6.2559045e-4f);
    const ull one2  = pk2(1.f, 1.f);
    __syncthreads();
    for (int i = tid; i < NS * 16; i += 256) {
        int s = i >> 4, n = i & 15;
        sB[s][n] = Bpb[(size_t)(t0 + s) * DS + n];
        sC[s][n] = Cpb[(size_t)(t0 + s) * DS + n];
    }
    float dtv[NS], xcv[NS];
#pragma unroll
    for (int s = 0; s < NS; s++) {
        dtv[s] = dtb[(size_t)(t0 + s) * DI];
        xcv[s] = xcb[(size_t)(t0 + s) * DI];
    }
    __syncthreads();

#pragma unroll
    for (int s = 0; s < NS; s++) {
        float dt_ = dtv[s], xc_ = xcv[s];
        float dtx = dt_ * xc_;
        ull dt2  = pk2(dt_, dt_);
        ull dtx2 = pk2(dtx, dtx);
        const ull* B2 = reinterpret_cast<const ull*>(sB[s]);
        const ull* C2 = reinterpret_cast<const ull*>(sC[s]);
#pragma unroll
        for (int p = 0; p < 8; p++) {
            ull w2 = mul2_(dt2, AL2[p]);
            ull t2 = mul2_(w2, w2);
            ull u2 = fma2_(t2, negc2, one2);
            float2 q = upk2(mul2_(w2, u2));
            ull dA2 = pk2(ex2_(q.x), ex2_(q.y));
            ull bx2 = mul2_(B2[p], dtx2);
            h2[p] = fma2_(h2[p], dA2, bx2);
        }
        if (s == 0) {  // t0 % 10 == 0 always: global norm event
            ull ss2 = pk2(0.f, 0.f);
#pragma unroll
            for (int p = 0; p < 8; p++) ss2 = fma2_(h2[p], h2[p], ss2);
            float2 sp = upk2(ss2);
            float ss = sp.x + sp.y;
#pragma unroll
            for (int o = 16; o; o >>= 1) ss += __shfl_xor_sync(0xffffffffu, ss, o);
            if ((tid & 31) == 0) warp_part[tid >> 5] = ss;
            __syncthreads();
            int par = cidx & 1;
            if (tid == 0) {
                float blk = 0.f;
#pragma unroll
                for (int w = 0; w < 8; w++) blk += warp_part[w];
                slot[par] = blk;
            }
            asm volatile("barrier.cluster.arrive.aligned;" ::: "memory");
            asm volatile("barrier.cluster.wait.aligned;" ::: "memory");
            if (tid == 0) {
                float tot = 0.f;
#pragma unroll
                for (int r = 0; r < 8; r++) {
                    uint32_t rem;
                    asm volatile("mapa.shared::cluster.u32 %0, %1, %2;"
                                 : "=r"(rem)
                                 : "r"(slot_u32 + (uint32_t)(par * 4)), "r"(r));
                    float v;
                    asm volatile("ld.shared::cluster.f32 %0, [%1];" : "=f"(v) : "r"(rem));
                    tot += v;
                }
                float nrm = sqrtf(tot);
                *s_fac = fminf(20.f / (nrm + 1e-8f), 1.f);
            }
            __syncthreads();
            ull fac2 = pk2(*s_fac, *s_fac);
#pragma unroll
            for (int p = 0; p < 8; p++) h2[p] = mul2_(h2[p], fac2);
        }
        ull y2 = pk2(Dv * xc_, 0.f);
#pragma unroll
        for (int p = 0; p < 8; p++) y2 = fma2_(h2[p], C2[p], y2);
        float2 yy = upk2(y2);
        yb[(size_t)(t0 + s) * DI] = yy.x + yy.y;
    }
}

__global__ void __cluster_dims__(8, 1, 1) __launch_bounds__(256)
scan_kernel(const float* __restrict__ A_log, const float* __restrict__ Dp)
{
    __shared__ float sB[10][16], sC[10][16];
    __shared__ float warp_part[8];
    __shared__ float slot[2];
    __shared__ float s_fac;

    int tid = threadIdx.x;
    int b = blockIdx.x >> 3;
    int rk = blockIdx.x & 7;
    int d = rk * 256 + tid;

    ull AL2[8], h2[8];
#pragma unroll
    for (int p = 0; p < 8; p++) {
        float a0 = A_log[(size_t)d * 16 + 2 * p];
        float a1 = A_log[(size_t)d * 16 + 2 * p + 1];
        float A0 = -expf(10.f * tanhf(0.1f * a0)) * 1.44269504f;
        float A1 = -expf(10.f * tanhf(0.1f * a1)) * 1.44269504f;
        AL2[p] = pk2(A0, A1);
        h2[p] = pk2(0.f, 0.f);
    }
    float Dv = Dp[d];

    const float* dtb = g_dt + (size_t)b * LSEQ * DI + d;
    const float* xcb = g_xc + (size_t)b * LSEQ * DI + d;
    float* yb = g_xssm + (size_t)b * LSEQ * DI + d;
    const float* Bpb = g_Bp + (size_t)b * LSEQ * DS;
    const float* Cpb = g_Cp + (size_t)b * LSEQ * DS;

    uint32_t slot_u32 = (uint32_t)__cvta_generic_to_shared(slot);

    for (int c = 0; c < 102; c++)
        scan_chunk<10>(c * 10, c, tid, h2, AL2, Dv, dtb, xcb, yb, Bpb, Cpb,
                       sB, sC, warp_part, slot, &s_fac, slot_u32);
    scan_chunk<4>(1020, 102, tid, h2, AL2, Dv, dtb, xcb, yb, Bpb, Cpb,
                  sB, sC, warp_part, slot, &s_fac, slot_u32);
}

// ------------------------- gate (-> bf16 hi/lo) -------------------------
__global__ void gate_kernel()
{
    size_t i4 = (size_t)blockIdx.x * blockDim.x + threadIdx.x;  // float4 index
    size_t i = i4 * 4;
    int token = (int)(i >> 11);
    int dd = (int)(i & (DI - 1));
    float4 g = *reinterpret_cast<const float4*>(g_proj + (size_t)token * (2 * DI) + DI + dd);
    float4 xs = *reinterpret_cast<const float4*>(g_xssm + i);
    float v0 = xs.x * (g.x / (1.f + expf(-g.x)));
    float v1 = xs.y * (g.y / (1.f + expf(-g.y)));
    float v2 = xs.z * (g.z / (1.f + expf(-g.z)));
    float v3 = xs.w * (g.w / (1.f + expf(-g.w)));
    __nv_bfloat162 h0, h1, l0, l1;
    split_bf16(v0, h0.x, l0.x); split_bf16(v1, h0.y, l0.y);
    split_bf16(v2, h1.x, l1.x); split_bf16(v3, h1.y, l1.y);
    reinterpret_cast<__nv_bfloat162*>(g_gate_h)[2 * i4]     = h0;
    reinterpret_cast<__nv_bfloat162*>(g_gate_h)[2 * i4 + 1] = h1;
    reinterpret_cast<__nv_bfloat162*>(g_gate_l)[2 * i4]     = l0;
    reinterpret_cast<__nv_bfloat162*>(g_gate_l)[2 * i4 + 1] = l1;
}

// ------------------------- launch -------------------------
extern "C" void kernel_launch(void* const* d_in, const int* in_sizes, int n_in,
                              void* d_out, int out_size)
{
    const float* x       = (const float*)d_in[0];
    const float* norm_w  = (const float*)d_in[1];
    const float* W_in    = (const float*)d_in[2];
    const float* conv_w  = (const float*)d_in[3];
    const float* conv_b  = (const float*)d_in[4];
    const float* W_dt    = (const float*)d_in[5];
    const float* b_dt    = (const float*)d_in[6];
    const float* W_B     = (const float*)d_in[7];
    const float* W_C     = (const float*)d_in[8];
    const float* A_log   = (const float*)d_in[9];
    const float* D_param = (const float*)d_in[10];
    const float* W_out   = (const float*)d_in[11];
    const float* r_scale = (const float*)d_in[12];
    float* out = (float*)d_out;

    void *p_proj, *p_dt;
    void *p_xnh, *p_xnl, *p_xch, *p_xcl, *p_gh, *p_gl;
    void *p_wih, *p_wil, *p_wdh, *p_wdl, *p_woh, *p_wol;
    cudaGetSymbolAddress(&p_proj, g_proj);
    cudaGetSymbolAddress(&p_dt, g_dt);
    cudaGetSymbolAddress(&p_xnh, g_xn_h);  cudaGetSymbolAddress(&p_xnl, g_xn_l);
    cudaGetSymbolAddress(&p_xch, g_xc_h);  cudaGetSymbolAddress(&p_xcl, g_xc_l);
    cudaGetSymbolAddress(&p_gh, g_gate_h); cudaGetSymbolAddress(&p_gl, g_gate_l);
    cudaGetSymbolAddress(&p_wih, g_Win_h); cudaGetSymbolAddress(&p_wil, g_Win_l);
    cudaGetSymbolAddress(&p_wdh, g_Wdt_h); cudaGetSymbolAddress(&p_wdl, g_Wdt_l);
    cudaGetSymbolAddress(&p_woh, g_Wout_h); cudaGetSymbolAddress(&p_wol, g_Wout_l);

    // weight hi/lo splits
    cvt_hl_kernel<<<(2 * DI * DM / 4) / 256, 256>>>(W_in, (__nv_bfloat16*)p_wih,
                                                    (__nv_bfloat16*)p_wil, 2 * DI * DM / 4);
    cvt_hl_kernel<<<(DI * DI / 4) / 256, 256>>>(W_dt, (__nv_bfloat16*)p_wdh,
                                                (__nv_bfloat16*)p_wdl, DI * DI / 4);
    cvt_hl_kernel<<<(DM * DI / 4) / 256, 256>>>(W_out, (__nv_bfloat16*)p_woh,
                                                (__nv_bfloat16*)p_wol, DM * DI / 4);
    // 1. RMSNorm -> bf16 hi/lo
    rmsnorm_kernel<<<NTOK, 256>>>(x, norm_w);
    // 2. in-projection (HMMA)
    gemm_hmma<0><<<dim3(4096 / 128, NTOK / 128), 256>>>(
        (const __nv_bfloat16*)p_xnh, (const __nv_bfloat16*)p_xnl,
        (const __nv_bfloat16*)p_wih, (const __nv_bfloat16*)p_wil,
        (float*)p_proj, 4096, 1024, nullptr, nullptr, nullptr);
    // 3. conv + silu
    conv_silu_kernel<<<NTOK, 256>>>(conv_w, conv_b);
    // 4. dt GEMM (HMMA, fused softplus+softclamp)
    gemm_hmma<1><<<dim3(DI / 128, NTOK / 128), 256>>>(
        (const __nv_bfloat16*)p_xch, (const __nv_bfloat16*)p_xcl,
        (const __nv_bfloat16*)p_wdh, (const __nv_bfloat16*)p_wdl,
        (float*)p_dt, DI, DI, b_dt, nullptr, nullptr);
    // 5. Bp / Cp
    bpcp_kernel<<<NTOK / 4, 256>>>(W_B, W_C);
    // 6. selective scan
    scan_kernel<<<16, 256>>>(A_log, D_param);
    // 7. gating -> bf16 hi/lo
    gate_kernel<<<(NTOK * DI / 4) / 256, 256>>>();
    // 8. out-projection + residual (HMMA)
    gemm_hmma<2><<<dim3(DM / 128, NTOK / 128), 256>>>(
        (const __nv_bfloat16*)p_gh, (const __nv_bfloat16*)p_gl,
        (const __nv_bfloat16*)p_woh, (const __nv_bfloat16*)p_wol,
        out, DM, DI, nullptr, x, r_scale);
}

// round 6
// speedup vs baseline: 3.0714x; 1.6083x over previous
#include <cuda_runtime.h>
#include <cuda_bf16.h>
#include <cstdint>
#include <cstddef>

#define NTOK 2048
#define DM   1024
#define DI   2048
#define DS   16
#define LSEQ 1024

typedef unsigned long long ull;

// ------------------------- scratch -------------------------
__device__ float g_proj[NTOK * 2 * DI];
__device__ float g_xc[NTOK * DI];
__device__ float g_dt[NTOK * DI];
__device__ float g_Bp[NTOK * DS];
__device__ float g_Cp[NTOK * DS];
__device__ float g_xssm[NTOK * DI];

__device__ __nv_bfloat16 g_xn_h[NTOK * DM];
__device__ __nv_bfloat16 g_xc_h[NTOK * DI];
__device__ __nv_bfloat16 g_gate_h[NTOK * DI];
__device__ __nv_bfloat16 g_Win_h[2 * DI * DM];
__device__ __nv_bfloat16 g_Wdt_h[DI * DI];
__device__ __nv_bfloat16 g_Wout_h[DM * DI];

// ------------------------- PTX helpers -------------------------
__device__ __forceinline__ uint32_t cvta_s(const void* p) {
    uint32_t a;
    asm("{.reg .u64 t; cvta.to.shared.u64 t, %1; cvt.u32.u64 %0, t;}" : "=r"(a) : "l"(p));
    return a;
}
__device__ __forceinline__ void cp_async16(uint32_t saddr, const void* gaddr) {
    asm volatile("cp.async.cg.shared.global [%0], [%1], 16;" :: "r"(saddr), "l"(gaddr));
}
#define CP_COMMIT() asm volatile("cp.async.commit_group;" ::: "memory")
#define CP_WAIT(n)  asm volatile("cp.async.wait_group %0;" :: "n"(n) : "memory")

__device__ __forceinline__ void ldsm4(uint32_t* r, uint32_t addr) {
    asm volatile("ldmatrix.sync.aligned.m8n8.x4.shared.b16 {%0,%1,%2,%3}, [%4];"
                 : "=r"(r[0]), "=r"(r[1]), "=r"(r[2]), "=r"(r[3]) : "r"(addr));
}
__device__ __forceinline__ void mma16816(float* c, const uint32_t* a, const uint32_t* b) {
    asm volatile("mma.sync.aligned.m16n8k16.row.col.f32.bf16.bf16.f32 "
                 "{%0,%1,%2,%3},{%4,%5,%6,%7},{%8,%9},{%0,%1,%2,%3};"
                 : "+f"(c[0]), "+f"(c[1]), "+f"(c[2]), "+f"(c[3])
                 : "r"(a[0]), "r"(a[1]), "r"(a[2]), "r"(a[3]), "r"(b[0]), "r"(b[1]));
}

__device__ __forceinline__ ull pk2(float lo, float hi) {
    ull r; asm("mov.b64 %0,{%1,%2};" : "=l"(r) : "f"(lo), "f"(hi)); return r;
}
__device__ __forceinline__ float2 upk2(ull v) {
    float2 f; asm("mov.b64 {%0,%1},%2;" : "=f"(f.x), "=f"(f.y) : "l"(v)); return f;
}
__device__ __forceinline__ ull fma2_(ull a, ull b, ull c) {
    ull d; asm("fma.rn.f32x2 %0,%1,%2,%3;" : "=l"(d) : "l"(a), "l"(b), "l"(c)); return d;
}
__device__ __forceinline__ ull mul2_(ull a, ull b) {
    ull d; asm("mul.rn.f32x2 %0,%1,%2;" : "=l"(d) : "l"(a), "l"(b)); return d;
}
__device__ __forceinline__ float ex2_(float x) {
    float y; asm("ex2.approx.f32 %0,%1;" : "=f"(y) : "f"(x)); return y;
}

// ------------------------- fp32 -> bf16 conversion -------------------------
__global__ void cvt_h_kernel(const float* __restrict__ src,
                             __nv_bfloat16* __restrict__ h, int n4)
{
    int i = blockIdx.x * blockDim.x + threadIdx.x;
    if (i >= n4) return;
    float4 v = reinterpret_cast<const float4*>(src)[i];
    __nv_bfloat162 h0, h1;
    h0.x = __float2bfloat16_rn(v.x); h0.y = __float2bfloat16_rn(v.y);
    h1.x = __float2bfloat16_rn(v.z); h1.y = __float2bfloat16_rn(v.w);
    reinterpret_cast<__nv_bfloat162*>(h)[2 * i]     = h0;
    reinterpret_cast<__nv_bfloat162*>(h)[2 * i + 1] = h1;
}

// ------------------------- rmsnorm (-> bf16) -------------------------
__global__ void rmsnorm_kernel(const float* __restrict__ x, const float* __restrict__ w)
{
    __shared__ float red[8];
    int token = blockIdx.x;
    int tid = threadIdx.x;  // 256
    float4 v = reinterpret_cast<const float4*>(x + (size_t)token * DM)[tid];
    float ss = v.x * v.x + v.y * v.y + v.z * v.z + v.w * v.w;
#pragma unroll
    for (int o = 16; o; o >>= 1) ss += __shfl_xor_sync(0xffffffffu, ss, o);
    if ((tid & 31) == 0) red[tid >> 5] = ss;
    __syncthreads();
    float tot = 0.f;
#pragma unroll
    for (int i = 0; i < 8; i++) tot += red[i];
    float r = rsqrtf(tot * (1.f / (float)DM) + 1e-6f);
    float4 wv = reinterpret_cast<const float4*>(w)[tid];
    __nv_bfloat162 h0, h1;
    h0.x = __float2bfloat16_rn(v.x * r * wv.x);
    h0.y = __float2bfloat16_rn(v.y * r * wv.y);
    h1.x = __float2bfloat16_rn(v.z * r * wv.z);
    h1.y = __float2bfloat16_rn(v.w * r * wv.w);
    size_t base = (size_t)token * (DM / 2) + tid * 2;
    reinterpret_cast<__nv_bfloat162*>(g_xn_h)[base]     = h0;
    reinterpret_cast<__nv_bfloat162*>(g_xn_h)[base + 1] = h1;
}

// ------------------------- HMMA bf16 GEMM (NT) -------------------------
// C[M,N] = A[M,K]*B[N,K]^T, bf16 in / fp32 accum. CTA 128x128, 8 warps 64x32,
// K-step 16, cp.async double buffer, 24-elem padded smem rows.
#define SROW 24
#define STILE (128 * SROW)

template <int MODE>
__global__ void __launch_bounds__(256, 2) gemm_hmma(
    const __nv_bfloat16* __restrict__ Ah, const __nv_bfloat16* __restrict__ Bh,
    float* __restrict__ Cg, int N, int K,
    const float* __restrict__ bias, const float* __restrict__ resid,
    const float* __restrict__ scale_ptr)
{
    __shared__ __nv_bfloat16 sm[2][2][STILE];   // 24 KB

    const int tid = threadIdx.x, wid = tid >> 5, lane = tid & 31;
    const int bm = blockIdx.y * 128, bn = blockIdx.x * 128;
    const int warp_m = wid >> 2, warp_n = wid & 3;

    float acc[4][4][4];
#pragma unroll
    for (int i = 0; i < 4; i++)
#pragma unroll
        for (int j = 0; j < 4; j++)
#pragma unroll
            for (int q = 0; q < 4; q++) acc[i][j][q] = 0.f;

    const __nv_bfloat16* srcs[2] = { Ah + (size_t)bm * K, Bh + (size_t)bn * K };

    const int row = tid >> 1, half = tid & 1;
    const uint32_t smb = cvta_s(sm);
    const uint32_t dst_off = (uint32_t)(row * SROW + half * 8) * 2;

    uint32_t a_off[4], b_off[2];
#pragma unroll
    for (int i = 0; i < 4; i++) {
        int r = warp_m * 64 + i * 16 + (lane & 15);
        a_off[i] = (uint32_t)(r * SROW + (lane >> 4) * 8) * 2;
    }
#pragma unroll
    for (int g = 0; g < 2; g++) {
        int n = warp_n * 32 + g * 16 + ((lane >> 4) & 1) * 8 + (lane & 7);
        b_off[g] = (uint32_t)(n * SROW + ((lane >> 3) & 1) * 8) * 2;
    }

    const int nst = K >> 4;
#pragma unroll
    for (int t = 0; t < 2; t++)
        cp_async16(smb + (uint32_t)(t * STILE) * 2 + dst_off,
                   srcs[t] + (size_t)row * K + half * 8);
    CP_COMMIT();

    for (int c = 0; c < nst; c++) {
        if (c + 1 < nst) {
            uint32_t bufb = smb + (uint32_t)(((c + 1) & 1) * 2 * STILE) * 2;
            const size_t goff = (size_t)row * K + (c + 1) * 16 + half * 8;
#pragma unroll
            for (int t = 0; t < 2; t++)
                cp_async16(bufb + (uint32_t)(t * STILE) * 2 + dst_off, srcs[t] + goff);
            CP_COMMIT();
            CP_WAIT(1);
        } else {
            CP_WAIT(0);
        }
        __syncthreads();

        const uint32_t bb = smb + (uint32_t)((c & 1) * 2 * STILE) * 2;
        uint32_t ah[4][4], bh[4][2];
#pragma unroll
        for (int i = 0; i < 4; i++) ldsm4(ah[i], bb + a_off[i]);
#pragma unroll
        for (int g = 0; g < 2; g++) {
            uint32_t r[4];
            ldsm4(r, bb + (uint32_t)STILE * 2 + b_off[g]);
            bh[2 * g][0] = r[0]; bh[2 * g][1] = r[1];
            bh[2 * g + 1][0] = r[2]; bh[2 * g + 1][1] = r[3];
        }
#pragma unroll
        for (int i = 0; i < 4; i++)
#pragma unroll
            for (int j = 0; j < 4; j++) mma16816(acc[i][j], ah[i], bh[j]);
        __syncthreads();
    }

    float scale = 0.f;
    if (MODE == 2) scale = 0.5f / (1.f + expf(-scale_ptr[0]));

#pragma unroll
    for (int i = 0; i < 4; i++)
#pragma unroll
        for (int j = 0; j < 4; j++) {
            int rr = bm + warp_m * 64 + i * 16 + (lane >> 2);
            int cc = bn + warp_n * 32 + j * 8 + (lane & 3) * 2;
#pragma unroll
            for (int hrow = 0; hrow < 2; hrow++) {
                size_t r = (size_t)(rr + hrow * 8);
                float v0 = acc[i][j][hrow * 2], v1 = acc[i][j][hrow * 2 + 1];
                if (MODE == 1) {
                    float p0 = v0 + bias[cc], p1 = v1 + bias[cc + 1];
                    float s0 = fmaxf(p0, 0.f) + log1pf(expf(-fabsf(p0)));
                    float s1 = fmaxf(p1, 0.f) + log1pf(expf(-fabsf(p1)));
                    v0 = tanhf((s0 - 0.0505f) * (0.5f / (0.0495f + 1e-8f))) * 0.099f + 0.0505f;
                    v1 = tanhf((s1 - 0.0505f) * (0.5f / (0.0495f + 1e-8f))) * 0.099f + 0.0505f;
                } else if (MODE == 2) {
                    v0 = resid[r * N + cc] + scale * v0;
                    v1 = resid[r * N + cc + 1] + scale * v1;
                }
                *reinterpret_cast<float2*>(Cg + r * N + cc) = make_float2(v0, v1);
            }
        }
}

// ------------------------- conv4 + SiLU (-> fp32 + bf16) -------------------------
__global__ void conv_silu_kernel(const float* __restrict__ conv_w, const float* __restrict__ conv_b)
{
    int token = blockIdx.x;
    int t = token & (LSEQ - 1);
    for (int d = threadIdx.x; d < DI; d += blockDim.x) {
        float4 w = *reinterpret_cast<const float4*>(conv_w + (size_t)d * 4);
        float acc = conv_b[d];
        const float* base = g_proj + (size_t)token * (2 * DI) + d;
        if (t >= 3) acc = fmaf(w.x, base[-3 * 2 * DI], acc);
        if (t >= 2) acc = fmaf(w.y, base[-2 * 2 * DI], acc);
        if (t >= 1) acc = fmaf(w.z, base[-1 * 2 * DI], acc);
        acc = fmaf(w.w, base[0], acc);
        float s = 1.f / (1.f + expf(-acc));
        float val = acc * s;
        size_t idx = (size_t)token * DI + d;
        g_xc[idx] = val;
        g_xc_h[idx] = __float2bfloat16_rn(val);
    }
}

// ------------------------- Bp / Cp projections -------------------------
__global__ void __launch_bounds__(256) bpcp_kernel(const float* __restrict__ W_B,
                                                   const float* __restrict__ W_C)
{
    __shared__ float sx[4][DI];
    int tok0 = blockIdx.x * 4;
    int tid = threadIdx.x;
    for (int i = tid; i < 4 * DI; i += 256) {
        int r = i >> 11, dd = i & (DI - 1);
        sx[r][dd] = g_xc[(size_t)(tok0 + r) * DI + dd];
    }
    __syncthreads();
    int wid = tid >> 5, lane = tid & 31;
#pragma unroll
    for (int oo = 0; oo < 4; oo++) {
        int o = wid + oo * 8;
        const float* Wr = (o < 16) ? (W_B + (size_t)o * DI) : (W_C + (size_t)(o - 16) * DI);
        float a0 = 0.f, a1 = 0.f, a2 = 0.f, a3 = 0.f;
        for (int dd = lane; dd < DI; dd += 32) {
            float w = Wr[dd];
            a0 = fmaf(w, sx[0][dd], a0);
            a1 = fmaf(w, sx[1][dd], a1);
            a2 = fmaf(w, sx[2][dd], a2);
            a3 = fmaf(w, sx[3][dd], a3);
        }
#pragma unroll
        for (int off = 16; off; off >>= 1) {
            a0 += __shfl_xor_sync(0xffffffffu, a0, off);
            a1 += __shfl_xor_sync(0xffffffffu, a1, off);
            a2 += __shfl_xor_sync(0xffffffffu, a2, off);
            a3 += __shfl_xor_sync(0xffffffffu, a3, off);
        }
        if (lane == 0) {
            float* outp = (o < 16) ? g_Bp : g_Cp;
            int oc = (o < 16) ? o : (o - 16);
            outp[(tok0 + 0) * DS + oc] = a0;
            outp[(tok0 + 1) * DS + oc] = a1;
            outp[(tok0 + 2) * DS + oc] = a2;
            outp[(tok0 + 3) * DS + oc] = a3;
        }
    }
}

// ------------------------- selective scan -------------------------
// One cluster per batch. 128 threads/CTA. CPT channels per thread.
// cluster size cs: 16 (CPT=1) or fallback 8 (CPT=2).
template <int NS, int CPT>
__device__ __forceinline__ void scan_chunk(
    int t0, int cidx, int tid, int cs, uint32_t rank,
    ull (*h2)[8], const ull (*AL2)[8], const float* Dv,
    const float* const* dtb, const float* const* xcb, float* const* yb,
    const float* Bpb, const float* Cpb,
    float (*sB)[16], float (*sC)[16],
    float* warp_part, float (*slotbuf)[16], float* s_fac, uint32_t slot_u32)
{
    __syncthreads();  // protect smem reuse across chunks
    for (int i = tid; i < NS * 16; i += 128) {
        int s = i >> 4, n = i & 15;
        sB[s][n] = Bpb[(size_t)(t0 + s) * DS + n];
        sC[s][n] = Cpb[(size_t)(t0 + s) * DS + n];
    }
    float dtv[CPT][NS], xcv[CPT][NS];
#pragma unroll
    for (int j = 0; j < CPT; j++)
#pragma unroll
        for (int s = 0; s < NS; s++) {
            dtv[j][s] = dtb[j][(size_t)(t0 + s) * DI];
            xcv[j][s] = xcb[j][(size_t)(t0 + s) * DI];
        }
    __syncthreads();

    const int lane = tid & 31, wid = tid >> 5;

#pragma unroll
    for (int s = 0; s < NS; s++) {
        const ull* B2 = reinterpret_cast<const ull*>(sB[s]);
        const ull* C2 = reinterpret_cast<const ull*>(sC[s]);
#pragma unroll
        for (int j = 0; j < CPT; j++) {
            float dt_ = dtv[j][s], xc_ = xcv[j][s];
            float dtx = dt_ * xc_;
            ull dt2  = pk2(dt_, dt_);
            ull dtx2 = pk2(dtx, dtx);
#pragma unroll
            for (int p = 0; p < 8; p++) {
                float2 q = upk2(mul2_(dt2, AL2[j][p]));   // dt * A * log2e
                ull dA2 = pk2(ex2_(q.x), ex2_(q.y));
                h2[j][p] = fma2_(h2[j][p], dA2, mul2_(B2[p], dtx2));
            }
        }
        if (s == 0) {  // t0 % 10 == 0 always: global norm event
            ull ss2 = pk2(0.f, 0.f);
#pragma unroll
            for (int j = 0; j < CPT; j++)
#pragma unroll
                for (int p = 0; p < 8; p++) ss2 = fma2_(h2[j][p], h2[j][p], ss2);
            float2 sp = upk2(ss2);
            float ss = sp.x + sp.y;
#pragma unroll
            for (int o = 16; o; o >>= 1) ss += __shfl_xor_sync(0xffffffffu, ss, o);
            if (lane == 0) warp_part[wid] = ss;
            __syncthreads();
            int par = cidx & 1;
            if (wid == 0) {
                float v = (lane < 4) ? warp_part[lane] : 0.f;
                v += __shfl_xor_sync(0xffffffffu, v, 1);
                v += __shfl_xor_sync(0xffffffffu, v, 2);   // block sum in all lanes
                if (lane < cs) {
                    uint32_t rem;
                    asm volatile("mapa.shared::cluster.u32 %0, %1, %2;"
                                 : "=r"(rem)
                                 : "r"(slot_u32 + (uint32_t)((par * 16 + (int)rank) * 4)),
                                   "r"(lane));
                    asm volatile("st.shared::cluster.f32 [%0], %1;"
                                 :: "r"(rem), "f"(v) : "memory");
                }
            }
            asm volatile("barrier.cluster.arrive.aligned;" ::: "memory");
            asm volatile("barrier.cluster.wait.aligned;" ::: "memory");
            if (wid == 0) {
                float v = (lane < cs) ? slotbuf[par][lane] : 0.f;
                v += __shfl_xor_sync(0xffffffffu, v, 8);
                v += __shfl_xor_sync(0xffffffffu, v, 4);
                v += __shfl_xor_sync(0xffffffffu, v, 2);
                v += __shfl_xor_sync(0xffffffffu, v, 1);
                if (lane == 0) *s_fac = fminf(20.f / (sqrtf(v) + 1e-8f), 1.f);
            }
            __syncthreads();
            float fac = *s_fac;
            ull fac2 = pk2(fac, fac);
#pragma unroll
            for (int j = 0; j < CPT; j++)
#pragma unroll
                for (int p = 0; p < 8; p++) h2[j][p] = mul2_(h2[j][p], fac2);
        }
#pragma unroll
        for (int j = 0; j < CPT; j++) {
            ull y2 = pk2(Dv[j] * xcv[j][s], 0.f);
#pragma unroll
            for (int p = 0; p < 8; p++) y2 = fma2_(h2[j][p], C2[p], y2);
            float2 yy = upk2(y2);
            yb[j][(size_t)(t0 + s) * DI] = yy.x + yy.y;
        }
    }
}

template <int CPT>
__global__ void __launch_bounds__(128) scan_kernel(const float* __restrict__ A_log,
                                                   const float* __restrict__ Dp, int cs)
{
    __shared__ float sB[10][16], sC[10][16];
    __shared__ float warp_part[4];
    __shared__ float slotbuf[2][16];
    __shared__ float s_fac;

    int tid = threadIdx.x;
    uint32_t rank;
    asm("mov.u32 %0, %%cluster_ctarank;" : "=r"(rank));
    int b = blockIdx.x / cs;

    ull AL2[CPT][8], h2[CPT][8];
    float Dv[CPT];
    const float* dtb[CPT];
    const float* xcb[CPT];
    float* yb[CPT];
#pragma unroll
    for (int j = 0; j < CPT; j++) {
        int d = (int)rank * (128 * CPT) + j * 128 + tid;
#pragma unroll
        for (int p = 0; p < 8; p++) {
            float a0 = A_log[(size_t)d * 16 + 2 * p];
            float a1 = A_log[(size_t)d * 16 + 2 * p + 1];
            float A0 = -expf(10.f * tanhf(0.1f * a0)) * 1.44269504f;
            float A1 = -expf(10.f * tanhf(0.1f * a1)) * 1.44269504f;
            AL2[j][p] = pk2(A0, A1);
            h2[j][p] = pk2(0.f, 0.f);
        }
        Dv[j] = Dp[d];
        dtb[j] = g_dt + (size_t)b * LSEQ * DI + d;
        xcb[j] = g_xc + (size_t)b * LSEQ * DI + d;
        yb[j]  = g_xssm + (size_t)b * LSEQ * DI + d;
    }
    const float* Bpb = g_Bp + (size_t)b * LSEQ * DS;
    const float* Cpb = g_Cp + (size_t)b * LSEQ * DS;

    uint32_t slot_u32 = (uint32_t)__cvta_generic_to_shared(slotbuf);

    for (int c = 0; c < 102; c++)
        scan_chunk<10, CPT>(c * 10, c, tid, cs, rank, h2, AL2, Dv, dtb, xcb, yb,
                            Bpb, Cpb, sB, sC, warp_part, slotbuf, &s_fac, slot_u32);
    scan_chunk<4, CPT>(1020, 102, tid, cs, rank, h2, AL2, Dv, dtb, xcb, yb,
                       Bpb, Cpb, sB, sC, warp_part, slotbuf, &s_fac, slot_u32);
}

// ------------------------- gate (-> bf16) -------------------------
__global__ void gate_kernel()
{
    size_t i4 = (size_t)blockIdx.x * blockDim.x + threadIdx.x;
    size_t i = i4 * 4;
    int token = (int)(i >> 11);
    int dd = (int)(i & (DI - 1));
    float4 g = *reinterpret_cast<const float4*>(g_proj + (size_t)token * (2 * DI) + DI + dd);
    float4 xs = *reinterpret_cast<const float4*>(g_xssm + i);
    __nv_bfloat162 h0, h1;
    h0.x = __float2bfloat16_rn(xs.x * (g.x / (1.f + expf(-g.x))));
    h0.y = __float2bfloat16_rn(xs.y * (g.y / (1.f + expf(-g.y))));
    h1.x = __float2bfloat16_rn(xs.z * (g.z / (1.f + expf(-g.z))));
    h1.y = __float2bfloat16_rn(xs.w * (g.w / (1.f + expf(-g.w))));
    reinterpret_cast<__nv_bfloat162*>(g_gate_h)[2 * i4]     = h0;
    reinterpret_cast<__nv_bfloat162*>(g_gate_h)[2 * i4 + 1] = h1;
}

// ------------------------- launch -------------------------
extern "C" void kernel_launch(void* const* d_in, const int* in_sizes, int n_in,
                              void* d_out, int out_size)
{
    const float* x       = (const float*)d_in[0];
    const float* norm_w  = (const float*)d_in[1];
    const float* W_in    = (const float*)d_in[2];
    const float* conv_w  = (const float*)d_in[3];
    const float* conv_b  = (const float*)d_in[4];
    const float* W_dt    = (const float*)d_in[5];
    const float* b_dt    = (const float*)d_in[6];
    const float* W_B     = (const float*)d_in[7];
    const float* W_C     = (const float*)d_in[8];
    const float* A_log   = (const float*)d_in[9];
    const float* D_param = (const float*)d_in[10];
    const float* W_out   = (const float*)d_in[11];
    const float* r_scale = (const float*)d_in[12];
    float* out = (float*)d_out;

    void *p_proj, *p_dt;
    void *p_xnh, *p_xch, *p_gh, *p_wih, *p_wdh, *p_woh;
    cudaGetSymbolAddress(&p_proj, g_proj);
    cudaGetSymbolAddress(&p_dt, g_dt);
    cudaGetSymbolAddress(&p_xnh, g_xn_h);
    cudaGetSymbolAddress(&p_xch, g_xc_h);
    cudaGetSymbolAddress(&p_gh, g_gate_h);
    cudaGetSymbolAddress(&p_wih, g_Win_h);
    cudaGetSymbolAddress(&p_wdh, g_Wdt_h);
    cudaGetSymbolAddress(&p_woh, g_Wout_h);

    // weight bf16 casts
    cvt_h_kernel<<<(2 * DI * DM / 4) / 256, 256>>>(W_in, (__nv_bfloat16*)p_wih, 2 * DI * DM / 4);
    cvt_h_kernel<<<(DI * DI / 4) / 256, 256>>>(W_dt, (__nv_bfloat16*)p_wdh, DI * DI / 4);
    cvt_h_kernel<<<(DM * DI / 4) / 256, 256>>>(W_out, (__nv_bfloat16*)p_woh, DM * DI / 4);
    // 1. RMSNorm
    rmsnorm_kernel<<<NTOK, 256>>>(x, norm_w);
    // 2. in-projection
    gemm_hmma<0><<<dim3(4096 / 128, NTOK / 128), 256>>>(
        (const __nv_bfloat16*)p_xnh, (const __nv_bfloat16*)p_wih,
        (float*)p_proj, 4096, 1024, nullptr, nullptr, nullptr);
    // 3. conv + silu
    conv_silu_kernel<<<NTOK, 256>>>(conv_w, conv_b);
    // 4. dt GEMM (fused softplus+softclamp)
    gemm_hmma<1><<<dim3(DI / 128, NTOK / 128), 256>>>(
        (const __nv_bfloat16*)p_xch, (const __nv_bfloat16*)p_wdh,
        (float*)p_dt, DI, DI, b_dt, nullptr, nullptr);
    // 5. Bp / Cp
    bpcp_kernel<<<NTOK / 4, 256>>>(W_B, W_C);
    // 6. selective scan: try cluster-16 (1 ch/thread); fallback cluster-8 (2 ch/thread)
    {
        cudaError_t e = cudaFuncSetAttribute(
            (const void*)scan_kernel<1>,
            cudaFuncAttributeNonPortableClusterSizeAllowed, 1);
        cudaLaunchConfig_t cfg = {};
        cudaLaunchAttribute at[1];
        at[0].id = cudaLaunchAttributeClusterDimension;
        cfg.attrs = at;
        cfg.numAttrs = 1;
        cfg.blockDim = dim3(128, 1, 1);
        cfg.stream = 0;
        if (e == cudaSuccess) {
            int cs = 16;
            at[0].val.clusterDim = {16, 1, 1};
            cfg.gridDim = dim3(32, 1, 1);
            cudaLaunchKernelEx(&cfg, scan_kernel<1>, A_log, D_param, cs);
        } else {
            (void)cudaGetLastError();
            int cs = 8;
            at[0].val.clusterDim = {8, 1, 1};
            cfg.gridDim = dim3(16, 1, 1);
            cudaLaunchKernelEx(&cfg, scan_kernel<2>, A_log, D_param, cs);
        }
    }
    // 7. gating
    gate_kernel<<<(NTOK * DI / 4) / 256, 256>>>();
    // 8. out-projection + residual
    gemm_hmma<2><<<dim3(DM / 128, NTOK / 128), 256>>>(
        (const __nv_bfloat16*)p_gh, (const __nv_bfloat16*)p_woh,
        out, DM, DI, nullptr, x, r_scale);
}

// round 11
// speedup vs baseline: 5.0436x; 1.6421x over previous
#include <cuda_runtime.h>
#include <cuda_bf16.h>
#include <cstdint>
#include <cstddef>

#define NTOK 2048
#define DM   1024
#define DI   2048
#define DS   16
#define LSEQ 1024

typedef unsigned long long ull;

// ------------------------- scratch -------------------------
__device__ float g_proj[NTOK * 2 * DI];
__device__ float g_xc[NTOK * DI];
__device__ float g_dt[NTOK * DI];
__device__ float g_Bp[NTOK * DS];
__device__ float g_Cp[NTOK * DS];
__device__ float g_xssm[NTOK * DI];

__device__ __nv_bfloat16 g_xn_h[NTOK * DM];
__device__ __nv_bfloat16 g_xc_h[NTOK * DI];
__device__ __nv_bfloat16 g_gate_h[NTOK * DI];
__device__ __nv_bfloat16 g_Win_h[2 * DI * DM];
__device__ __nv_bfloat16 g_Wdt_h[DI * DI];
__device__ __nv_bfloat16 g_Wout_h[DM * DI];

// ------------------------- PTX helpers -------------------------
__device__ __forceinline__ uint32_t cvta_s(const void* p) {
    uint32_t a;
    asm("{.reg .u64 t; cvta.to.shared.u64 t, %1; cvt.u32.u64 %0, t;}" : "=r"(a) : "l"(p));
    return a;
}
__device__ __forceinline__ void cp_async16(uint32_t saddr, const void* gaddr) {
    asm volatile("cp.async.cg.shared.global [%0], [%1], 16;" :: "r"(saddr), "l"(gaddr));
}
#define CP_COMMIT() asm volatile("cp.async.commit_group;" ::: "memory")
#define CP_WAIT(n)  asm volatile("cp.async.wait_group %0;" :: "n"(n) : "memory")

__device__ __forceinline__ void ldsm4(uint32_t* r, uint32_t addr) {
    asm volatile("ldmatrix.sync.aligned.m8n8.x4.shared.b16 {%0,%1,%2,%3}, [%4];"
                 : "=r"(r[0]), "=r"(r[1]), "=r"(r[2]), "=r"(r[3]) : "r"(addr));
}
__device__ __forceinline__ void mma16816(float* c, const uint32_t* a, const uint32_t* b) {
    asm volatile("mma.sync.aligned.m16n8k16.row.col.f32.bf16.bf16.f32 "
                 "{%0,%1,%2,%3},{%4,%5,%6,%7},{%8,%9},{%0,%1,%2,%3};"
                 : "+f"(c[0]), "+f"(c[1]), "+f"(c[2]), "+f"(c[3])
                 : "r"(a[0]), "r"(a[1]), "r"(a[2]), "r"(a[3]), "r"(b[0]), "r"(b[1]));
}

__device__ __forceinline__ ull pk2(float lo, float hi) {
    ull r; asm("mov.b64 %0,{%1,%2};" : "=l"(r) : "f"(lo), "f"(hi)); return r;
}
__device__ __forceinline__ float2 upk2(ull v) {
    float2 f; asm("mov.b64 {%0,%1},%2;" : "=f"(f.x), "=f"(f.y) : "l"(v)); return f;
}
__device__ __forceinline__ ull fma2_(ull a, ull b, ull c) {
    ull d; asm("fma.rn.f32x2 %0,%1,%2,%3;" : "=l"(d) : "l"(a), "l"(b), "l"(c)); return d;
}
__device__ __forceinline__ ull mul2_(ull a, ull b) {
    ull d; asm("mul.rn.f32x2 %0,%1,%2;" : "=l"(d) : "l"(a), "l"(b)); return d;
}
__device__ __forceinline__ float ex2_(float x) {
    float y; asm("ex2.approx.f32 %0,%1;" : "=f"(y) : "f"(x)); return y;
}

#define MBAR_INIT(addr, cnt) \
    asm volatile("mbarrier.init.shared.b64 [%0], %1;" :: "r"(addr), "r"(cnt) : "memory")

#define MBAR_WAIT_CLU(addr, par) do {                                               \
    uint32_t _m = (addr); uint32_t _p = (par); uint32_t _d;                         \
    asm volatile("{\n\t.reg .pred p;\n\t"                                           \
        "mbarrier.try_wait.parity.acquire.cluster.shared::cta.b64 p, [%1], %2;\n\t" \
        "selp.b32 %0,1,0,p;\n\t}" : "=r"(_d) : "r"(_m), "r"(_p) : "memory");        \
    if (!_d) {                                                                      \
        asm volatile("{\n\t.reg .pred P1;\n\t"                                      \
        "WLC_%=:\n\t"                                                               \
        "mbarrier.try_wait.parity.acquire.cluster.shared::cta.b64 P1, [%0], %1, 0x989680;\n\t" \
        "@P1 bra.uni WDC_%=;\n\t"                                                   \
        "bra.uni WLC_%=;\n\t"                                                       \
        "WDC_%=:\n\t}" :: "r"(_m), "r"(_p) : "memory");                             \
    } } while (0)

#define ST_REMOTE_F32(laddr, rnk, val) \
    asm volatile("{.reg .b32 ra; mapa.shared::cluster.u32 ra, %0, %1;" \
                 " st.shared::cluster.f32 [ra], %2;}" \
                 :: "r"(laddr), "r"(rnk), "f"(val) : "memory")

#define MBAR_ARRIVE_REMOTE(laddr, rnk) \
    asm volatile("{.reg .b32 ra; mapa.shared::cluster.u32 ra, %0, %1;" \
                 " mbarrier.arrive.shared::cluster.b64 _, [ra];}" \
                 :: "r"(laddr), "r"(rnk) : "memory")

// ------------------------- fp32 -> bf16 conversion -------------------------
__global__ void cvt_h_kernel(const float* __restrict__ src,
                             __nv_bfloat16* __restrict__ h, int n4)
{
    int i = blockIdx.x * blockDim.x + threadIdx.x;
    if (i >= n4) return;
    float4 v = reinterpret_cast<const float4*>(src)[i];
    __nv_bfloat162 h0, h1;
    h0.x = __float2bfloat16_rn(v.x); h0.y = __float2bfloat16_rn(v.y);
    h1.x = __float2bfloat16_rn(v.z); h1.y = __float2bfloat16_rn(v.w);
    reinterpret_cast<__nv_bfloat162*>(h)[2 * i]     = h0;
    reinterpret_cast<__nv_bfloat162*>(h)[2 * i + 1] = h1;
}

// ------------------------- rmsnorm (-> bf16) -------------------------
__global__ void rmsnorm_kernel(const float* __restrict__ x, const float* __restrict__ w)
{
    __shared__ float red[8];
    int token = blockIdx.x;
    int tid = threadIdx.x;  // 256
    float4 v = reinterpret_cast<const float4*>(x + (size_t)token * DM)[tid];
    float ss = v.x * v.x + v.y * v.y + v.z * v.z + v.w * v.w;
#pragma unroll
    for (int o = 16; o; o >>= 1) ss += __shfl_xor_sync(0xffffffffu, ss, o);
    if ((tid & 31) == 0) red[tid >> 5] = ss;
    __syncthreads();
    float tot = 0.f;
#pragma unroll
    for (int i = 0; i < 8; i++) tot += red[i];
    float r = rsqrtf(tot * (1.f / (float)DM) + 1e-6f);
    float4 wv = reinterpret_cast<const float4*>(w)[tid];
    __nv_bfloat162 h0, h1;
    h0.x = __float2bfloat16_rn(v.x * r * wv.x);
    h0.y = __float2bfloat16_rn(v.y * r * wv.y);
    h1.x = __float2bfloat16_rn(v.z * r * wv.z);
    h1.y = __float2bfloat16_rn(v.w * r * wv.w);
    size_t base = (size_t)token * (DM / 2) + tid * 2;
    reinterpret_cast<__nv_bfloat162*>(g_xn_h)[base]     = h0;
    reinterpret_cast<__nv_bfloat162*>(g_xn_h)[base + 1] = h1;
}

// ------------------------- HMMA bf16 GEMM (NT), 4-stage pipeline -------------------------
#define SROW 24
#define STILE (128 * SROW)

template <int MODE>
__global__ void __launch_bounds__(256, 2) gemm_hmma(
    const __nv_bfloat16* __restrict__ Ah, const __nv_bfloat16* __restrict__ Bh,
    float* __restrict__ Cg, int N, int K,
    const float* __restrict__ bias, const float* __restrict__ resid,
    const float* __restrict__ scale_ptr)
{
    __shared__ __nv_bfloat16 sm[4][2][STILE];   // exactly 48 KB

    const int tid = threadIdx.x, wid = tid >> 5, lane = tid & 31;
    const int bm = blockIdx.y * 128, bn = blockIdx.x * 128;
    const int warp_m = wid >> 2, warp_n = wid & 3;

    float acc[4][4][4];
#pragma unroll
    for (int i = 0; i < 4; i++)
#pragma unroll
        for (int j = 0; j < 4; j++)
#pragma unroll
            for (int q = 0; q < 4; q++) acc[i][j][q] = 0.f;

    const __nv_bfloat16* srcs[2] = { Ah + (size_t)bm * K, Bh + (size_t)bn * K };

    const int row = tid >> 1, half = tid & 1;
    const uint32_t smb = cvta_s(sm);
    const uint32_t dst_off = (uint32_t)(row * SROW + half * 8) * 2;

    uint32_t a_off[4], b_off[2];
#pragma unroll
    for (int i = 0; i < 4; i++) {
        int r = warp_m * 64 + i * 16 + (lane & 15);
        a_off[i] = (uint32_t)(r * SROW + (lane >> 4) * 8) * 2;
    }
#pragma unroll
    for (int g = 0; g < 2; g++) {
        int n = warp_n * 32 + g * 16 + ((lane >> 4) & 1) * 8 + (lane & 7);
        b_off[g] = (uint32_t)(n * SROW + ((lane >> 3) & 1) * 8) * 2;
    }

    const int nst = K >> 4;
    // prologue: stages 0..2
#pragma unroll
    for (int st = 0; st < 3; st++) {
        uint32_t bufb = smb + (uint32_t)(st * 2 * STILE) * 2;
        const size_t goff = (size_t)row * K + st * 16 + half * 8;
#pragma unroll
        for (int t = 0; t < 2; t++)
            cp_async16(bufb + (uint32_t)(t * STILE) * 2 + dst_off, srcs[t] + goff);
        CP_COMMIT();
    }

    for (int c = 0; c < nst; c++) {
        CP_WAIT(2);
        __syncthreads();
        if (c + 3 < nst) {
            uint32_t bufb = smb + (uint32_t)(((c + 3) & 3) * 2 * STILE) * 2;
            const size_t goff = (size_t)row * K + (c + 3) * 16 + half * 8;
#pragma unroll
            for (int t = 0; t < 2; t++)
                cp_async16(bufb + (uint32_t)(t * STILE) * 2 + dst_off, srcs[t] + goff);
        }
        CP_COMMIT();   // always commit (possibly empty group) to keep counts aligned

        const uint32_t bb = smb + (uint32_t)((c & 3) * 2 * STILE) * 2;
        uint32_t ah[4][4], bh[4][2];
#pragma unroll
        for (int i = 0; i < 4; i++) ldsm4(ah[i], bb + a_off[i]);
#pragma unroll
        for (int g = 0; g < 2; g++) {
            uint32_t r[4];
            ldsm4(r, bb + (uint32_t)STILE * 2 + b_off[g]);
            bh[2 * g][0] = r[0]; bh[2 * g][1] = r[1];
            bh[2 * g + 1][0] = r[2]; bh[2 * g + 1][1] = r[3];
        }
#pragma unroll
        for (int i = 0; i < 4; i++)
#pragma unroll
            for (int j = 0; j < 4; j++) mma16816(acc[i][j], ah[i], bh[j]);
    }

    float scale = 0.f;
    if (MODE == 2) scale = 0.5f / (1.f + expf(-scale_ptr[0]));

#pragma unroll
    for (int i = 0; i < 4; i++)
#pragma unroll
        for (int j = 0; j < 4; j++) {
            int rr = bm + warp_m * 64 + i * 16 + (lane >> 2);
            int cc = bn + warp_n * 32 + j * 8 + (lane & 3) * 2;
#pragma unroll
            for (int hrow = 0; hrow < 2; hrow++) {
                size_t r = (size_t)(rr + hrow * 8);
                float v0 = acc[i][j][hrow * 2], v1 = acc[i][j][hrow * 2 + 1];
                if (MODE == 1) {
                    float p0 = v0 + bias[cc], p1 = v1 + bias[cc + 1];
                    float s0 = fmaxf(p0, 0.f) + log1pf(expf(-fabsf(p0)));
                    float s1 = fmaxf(p1, 0.f) + log1pf(expf(-fabsf(p1)));
                    v0 = tanhf((s0 - 0.0505f) * (0.5f / (0.0495f + 1e-8f))) * 0.099f + 0.0505f;
                    v1 = tanhf((s1 - 0.0505f) * (0.5f / (0.0495f + 1e-8f))) * 0.099f + 0.0505f;
                } else if (MODE == 2) {
                    v0 = resid[r * N + cc] + scale * v0;
                    v1 = resid[r * N + cc + 1] + scale * v1;
                }
                *reinterpret_cast<float2*>(Cg + r * N + cc) = make_float2(v0, v1);
            }
        }
}

// ------------------------- conv4 + SiLU (-> fp32 + bf16) -------------------------
__global__ void conv_silu_kernel(const float* __restrict__ conv_w, const float* __restrict__ conv_b)
{
    int token = blockIdx.x;
    int t = token & (LSEQ - 1);
    for (int d = threadIdx.x; d < DI; d += blockDim.x) {
        float4 w = *reinterpret_cast<const float4*>(conv_w + (size_t)d * 4);
        float acc = conv_b[d];
        const float* base = g_proj + (size_t)token * (2 * DI) + d;
        if (t >= 3) acc = fmaf(w.x, base[-3 * 2 * DI], acc);
        if (t >= 2) acc = fmaf(w.y, base[-2 * 2 * DI], acc);
        if (t >= 1) acc = fmaf(w.z, base[-1 * 2 * DI], acc);
        acc = fmaf(w.w, base[0], acc);
        float s = 1.f / (1.f + expf(-acc));
        float val = acc * s;
        size_t idx = (size_t)token * DI + d;
        g_xc[idx] = val;
        g_xc_h[idx] = __float2bfloat16_rn(val);
    }
}

// ------------------------- Bp / Cp projections -------------------------
__global__ void __launch_bounds__(256) bpcp_kernel(const float* __restrict__ W_B,
                                                   const float* __restrict__ W_C)
{
    __shared__ float sx[4][DI];
    int tok0 = blockIdx.x * 4;
    int tid = threadIdx.x;
    for (int i = tid; i < 4 * DI; i += 256) {
        int r = i >> 11, dd = i & (DI - 1);
        sx[r][dd] = g_xc[(size_t)(tok0 + r) * DI + dd];
    }
    __syncthreads();
    int wid = tid >> 5, lane = tid & 31;
#pragma unroll
    for (int oo = 0; oo < 4; oo++) {
        int o = wid + oo * 8;
        const float* Wr = (o < 16) ? (W_B + (size_t)o * DI) : (W_C + (size_t)(o - 16) * DI);
        float a0 = 0.f, a1 = 0.f, a2 = 0.f, a3 = 0.f;
        for (int dd = lane; dd < DI; dd += 32) {
            float w = Wr[dd];
            a0 = fmaf(w, sx[0][dd], a0);
            a1 = fmaf(w, sx[1][dd], a1);
            a2 = fmaf(w, sx[2][dd], a2);
            a3 = fmaf(w, sx[3][dd], a3);
        }
#pragma unroll
        for (int off = 16; off; off >>= 1) {
            a0 += __shfl_xor_sync(0xffffffffu, a0, off);
            a1 += __shfl_xor_sync(0xffffffffu, a1, off);
            a2 += __shfl_xor_sync(0xffffffffu, a2, off);
            a3 += __shfl_xor_sync(0xffffffffu, a3, off);
        }
        if (lane == 0) {
            float* outp = (o < 16) ? g_Bp : g_Cp;
            int oc = (o < 16) ? o : (o - 16);
            outp[(tok0 + 0) * DS + oc] = a0;
            outp[(tok0 + 1) * DS + oc] = a1;
            outp[(tok0 + 2) * DS + oc] = a2;
            outp[(tok0 + 3) * DS + oc] = a3;
        }
    }
}

// ------------------------- selective scan -------------------------
// One cluster per batch; 128 threads/CTA; CPT channels/thread.
// dt/xc/B/C staged via cp.async double buffer. dA: 2 pairs polynomial (FMA),
// 6 pairs ex2 (MUFU). Norm allreduce via DSMEM mbarrier (parity-phased).
template <int CPT>
__global__ void __launch_bounds__(128) scan_kernel(const float* __restrict__ A_log,
                                                   const float* __restrict__ Dp, int cs)
{
    __shared__ __align__(16) float sDT[2][10][128 * CPT];
    __shared__ __align__(16) float sXC[2][10][128 * CPT];
    __shared__ __align__(16) float sB[2][10][16];
    __shared__ __align__(16) float sC[2][10][16];
    __shared__ float warp_part[4];
    __shared__ __align__(8) float slotbuf[2][16];
    __shared__ float s_fac;
    __shared__ __align__(8) ull mbar;

    const int tid = threadIdx.x;
    const int lane = tid & 31, wid = tid >> 5;
    uint32_t rank; asm("mov.u32 %0, %%cluster_ctarank;" : "=r"(rank));
    const int b = blockIdx.x / cs;
    const int d0 = (int)rank * 128 * CPT;

    const uint32_t mbar_u32 = cvta_s(&mbar);
    const uint32_t slot_u32 = cvta_s(slotbuf);
    if (tid == 0) MBAR_INIT(mbar_u32, (uint32_t)cs);
    asm volatile("barrier.cluster.arrive.aligned;" ::: "memory");
    asm volatile("barrier.cluster.wait.aligned;" ::: "memory");

    ull ALn[CPT][2], ALe[CPT][6], h2[CPT][8];
    float Dv[CPT];
    float* yb[CPT];
#pragma unroll
    for (int j = 0; j < CPT; j++) {
        int d = d0 + j * 128 + tid;
#pragma unroll
        for (int p = 0; p < 8; p++) {
            float a0 = A_log[(size_t)d * 16 + 2 * p];
            float a1 = A_log[(size_t)d * 16 + 2 * p + 1];
            float A0 = -expf(10.f * tanhf(0.1f * a0));
            float A1 = -expf(10.f * tanhf(0.1f * a1));
            if (p < 2) ALn[j][p] = pk2(A0, A1);
            else       ALe[j][p - 2] = pk2(A0 * 1.44269504f, A1 * 1.44269504f);
            h2[j][p] = pk2(0.f, 0.f);
        }
        Dv[j] = Dp[d];
        yb[j] = g_xssm + (size_t)b * LSEQ * DI + d;
    }
    const float* dt_base = g_dt + (size_t)b * LSEQ * DI + d0;
    const float* xc_base = g_xc + (size_t)b * LSEQ * DI + d0;
    const float* Bp_base = g_Bp + (size_t)b * LSEQ * DS;
    const float* Cp_base = g_Cp + (size_t)b * LSEQ * DS;

    const uint32_t sdt_a = cvta_s(sDT), sxc_a = cvta_s(sXC);
    const uint32_t sb_a = cvta_s(sB), sc_a = cvta_s(sC);
    const int R16 = 32 * CPT;

    auto stage = [&](int cidx) {
        int buf = cidx & 1;
        int rows = (cidx == 102) ? 4 : 10;
        int t0 = cidx * 10;
        for (int i = tid; i < rows * R16; i += 128) {
            int s = i / R16, u = i % R16;
            cp_async16(sdt_a + (uint32_t)((buf * 10 + s) * R16 + u) * 16,
                       dt_base + (size_t)(t0 + s) * DI + u * 4);
            cp_async16(sxc_a + (uint32_t)((buf * 10 + s) * R16 + u) * 16,
                       xc_base + (size_t)(t0 + s) * DI + u * 4);
        }
        for (int i = tid; i < rows * 4; i += 128) {
            int s = i >> 2, u = i & 3;
            cp_async16(sb_a + (uint32_t)((buf * 10 + s) * 4 + u) * 16,
                       Bp_base + (size_t)(t0 + s) * DS + u * 4);
            cp_async16(sc_a + (uint32_t)((buf * 10 + s) * 4 + u) * 16,
                       Cp_base + (size_t)(t0 + s) * DS + u * 4);
        }
        CP_COMMIT();
    };

    const ull k24 = pk2(1.f / 24.f, 1.f / 24.f);
    const ull k6  = pk2(1.f / 6.f,  1.f / 6.f);
    const ull kh  = pk2(0.5f, 0.5f);
    const ull k1  = pk2(1.f, 1.f);

    stage(0);

    auto chunk_body = [&](int c, auto NSc) {
        constexpr int NS = decltype(NSc)::value;
        const int bc = c & 1;
        const int t0 = c * 10;
        float dtv[CPT][NS], xcv[CPT][NS];
#pragma unroll
        for (int j = 0; j < CPT; j++)
#pragma unroll
            for (int s = 0; s < NS; s++) {
                dtv[j][s] = sDT[bc][s][j * 128 + tid];
                xcv[j][s] = sXC[bc][s][j * 128 + tid];
            }

#pragma unroll
        for (int s = 0; s < NS; s++) {
            const ull* B2 = reinterpret_cast<const ull*>(sB[bc][s]);
            const ull* C2 = reinterpret_cast<const ull*>(sC[bc][s]);
#pragma unroll
            for (int j = 0; j < CPT; j++) {
                float dt_ = dtv[j][s], xc_ = xcv[j][s];
                float dtx = dt_ * xc_;
                ull dt2 = pk2(dt_, dt_), dtx2 = pk2(dtx, dtx);
#pragma unroll
                for (int p = 0; p < 2; p++) {       // polynomial pairs (FMA pipe)
                    ull w = mul2_(dt2, ALn[j][p]);
                    ull e = fma2_(w, k24, k6);
                    e = fma2_(e, w, kh);
                    e = fma2_(e, w, k1);
                    e = fma2_(e, w, k1);
                    h2[j][p] = fma2_(h2[j][p], e, mul2_(B2[p], dtx2));
                }
#pragma unroll
                for (int p = 2; p < 8; p++) {       // ex2 pairs (MUFU pipe)
                    float2 ww = upk2(mul2_(dt2, ALe[j][p - 2]));
                    ull dA = pk2(ex2_(ww.x), ex2_(ww.y));
                    h2[j][p] = fma2_(h2[j][p], dA, mul2_(B2[p], dtx2));
                }
            }
            if (s == 0) {  // norm event (t0 % 10 == 0 always)
                ull ss2 = pk2(0.f, 0.f);
#pragma unroll
                for (int j = 0; j < CPT; j++)
#pragma unroll
                    for (int p = 0; p < 8; p++) ss2 = fma2_(h2[j][p], h2[j][p], ss2);
                float2 sp = upk2(ss2);
                float ss = sp.x + sp.y;
#pragma unroll
                for (int o = 16; o; o >>= 1) ss += __shfl_xor_sync(0xffffffffu, ss, o);
                if (lane == 0) warp_part[wid] = ss;
                __syncthreads();
                int par = c & 1;
                if (wid == 0) {
                    float v = warp_part[lane & 3];
                    v += __shfl_xor_sync(0xffffffffu, v, 1);
                    v += __shfl_xor_sync(0xffffffffu, v, 2);  // total in ALL lanes
                    if (lane < cs) {
                        uint32_t myslot = slot_u32 + (uint32_t)((par * 16 + (int)rank) * 4);
                        ST_REMOTE_F32(myslot, (uint32_t)lane, v);
                        MBAR_ARRIVE_REMOTE(mbar_u32, (uint32_t)lane);
                    }
                    MBAR_WAIT_CLU(mbar_u32, (uint32_t)(c & 1));
                    float w = (lane < cs) ? slotbuf[par][lane] : 0.f;
                    w += __shfl_xor_sync(0xffffffffu, w, 8);
                    w += __shfl_xor_sync(0xffffffffu, w, 4);
                    w += __shfl_xor_sync(0xffffffffu, w, 2);
                    w += __shfl_xor_sync(0xffffffffu, w, 1);
                    if (lane == 0) s_fac = fminf(20.f / (sqrtf(w) + 1e-8f), 1.f);
                }
                __syncthreads();
                float fac = s_fac;
                ull fac2 = pk2(fac, fac);
#pragma unroll
                for (int j = 0; j < CPT; j++)
#pragma unroll
                    for (int p = 0; p < 8; p++) h2[j][p] = mul2_(h2[j][p], fac2);
            }
#pragma unroll
            for (int j = 0; j < CPT; j++) {
                ull y2 = pk2(Dv[j] * xcv[j][s], 0.f);
#pragma unroll
                for (int p = 0; p < 8; p++) y2 = fma2_(h2[j][p], C2[p], y2);
                float2 yy = upk2(y2);
                yb[j][(size_t)(t0 + s) * DI] = yy.x + yy.y;
            }
        }
    };

    for (int c = 0; c <= 102; c++) {
        if (c < 102) { stage(c + 1); CP_WAIT(1); }
        else         { CP_WAIT(0); }
        __syncthreads();
        if (c < 102) chunk_body(c, std::integral_constant<int, 10>{});
        else         chunk_body(c, std::integral_constant<int, 4>{});
    }
}

// ------------------------- gate (-> bf16) -------------------------
__global__ void gate_kernel()
{
    size_t i4 = (size_t)blockIdx.x * blockDim.x + threadIdx.x;
    size_t i = i4 * 4;
    int token = (int)(i >> 11);
    int dd = (int)(i & (DI - 1));
    float4 g = *reinterpret_cast<const float4*>(g_proj + (size_t)token * (2 * DI) + DI + dd);
    float4 xs = *reinterpret_cast<const float4*>(g_xssm + i);
    __nv_bfloat162 h0, h1;
    h0.x = __float2bfloat16_rn(xs.x * (g.x / (1.f + expf(-g.x))));
    h0.y = __float2bfloat16_rn(xs.y * (g.y / (1.f + expf(-g.y))));
    h1.x = __float2bfloat16_rn(xs.z * (g.z / (1.f + expf(-g.z))));
    h1.y = __float2bfloat16_rn(xs.w * (g.w / (1.f + expf(-g.w))));
    reinterpret_cast<__nv_bfloat162*>(g_gate_h)[2 * i4]     = h0;
    reinterpret_cast<__nv_bfloat162*>(g_gate_h)[2 * i4 + 1] = h1;
}

#include <type_traits>
namespace std { }  // (integral_constant via <type_traits>)

// ------------------------- launch -------------------------
extern "C" void kernel_launch(void* const* d_in, const int* in_sizes, int n_in,
                              void* d_out, int out_size)
{
    const float* x       = (const float*)d_in[0];
    const float* norm_w  = (const float*)d_in[1];
    const float* W_in    = (const float*)d_in[2];
    const float* conv_w  = (const float*)d_in[3];
    const float* conv_b  = (const float*)d_in[4];
    const float* W_dt    = (const float*)d_in[5];
    const float* b_dt    = (const float*)d_in[6];
    const float* W_B     = (const float*)d_in[7];
    const float* W_C     = (const float*)d_in[8];
    const float* A_log   = (const float*)d_in[9];
    const float* D_param = (const float*)d_in[10];
    const float* W_out   = (const float*)d_in[11];
    const float* r_scale = (const float*)d_in[12];
    float* out = (float*)d_out;

    void *p_proj, *p_dt;
    void *p_xnh, *p_xch, *p_gh, *p_wih, *p_wdh, *p_woh;
    cudaGetSymbolAddress(&p_proj, g_proj);
    cudaGetSymbolAddress(&p_dt, g_dt);
    cudaGetSymbolAddress(&p_xnh, g_xn_h);
    cudaGetSymbolAddress(&p_xch, g_xc_h);
    cudaGetSymbolAddress(&p_gh, g_gate_h);
    cudaGetSymbolAddress(&p_wih, g_Win_h);
    cudaGetSymbolAddress(&p_wdh, g_Wdt_h);
    cudaGetSymbolAddress(&p_woh, g_Wout_h);

    // one-time stream/event creation (no device memory involved)
    static cudaStream_t sA = nullptr, sB2 = nullptr;
    static cudaEvent_t ev[6] = {};
    if (!sA) {
        cudaStreamCreateWithFlags(&sA, cudaStreamNonBlocking);
        cudaStreamCreateWithFlags(&sB2, cudaStreamNonBlocking);
        for (int i = 0; i < 6; i++) cudaEventCreateWithFlags(&ev[i], cudaEventDisableTiming);
    }

    // fork sA for weight conversions
    cudaEventRecord(ev[0], 0);
    cudaStreamWaitEvent(sA, ev[0], 0);
    cvt_h_kernel<<<(2 * DI * DM / 4) / 256, 256, 0, sA>>>(W_in, (__nv_bfloat16*)p_wih,
                                                          2 * DI * DM / 4);
    cudaEventRecord(ev[1], sA);
    cvt_h_kernel<<<(DI * DI / 4) / 256, 256, 0, sA>>>(W_dt, (__nv_bfloat16*)p_wdh, DI * DI / 4);
    cudaEventRecord(ev[2], sA);
    cvt_h_kernel<<<(DM * DI / 4) / 256, 256, 0, sA>>>(W_out, (__nv_bfloat16*)p_woh, DM * DI / 4);
    cudaEventRecord(ev[3], sA);

    // main stream
    rmsnorm_kernel<<<NTOK, 256>>>(x, norm_w);
    cudaStreamWaitEvent(0, ev[1], 0);
    gemm_hmma<0><<<dim3(4096 / 128, NTOK / 128), 256>>>(
        (const __nv_bfloat16*)p_xnh, (const __nv_bfloat16*)p_wih,
        (float*)p_proj, 4096, 1024, nullptr, nullptr, nullptr);
    conv_silu_kernel<<<NTOK, 256>>>(conv_w, conv_b);

    // fork bpcp in parallel with dt GEMM
    cudaEventRecord(ev[4], 0);
    cudaStreamWaitEvent(sB2, ev[4], 0);
    bpcp_kernel<<<NTOK / 4, 256, 0, sB2>>>(W_B, W_C);
    cudaEventRecord(ev[5], sB2);

    cudaStreamWaitEvent(0, ev[2], 0);
    gemm_hmma<1><<<dim3(DI / 128, NTOK / 128), 256>>>(
        (const __nv_bfloat16*)p_xch, (const __nv_bfloat16*)p_wdh,
        (float*)p_dt, DI, DI, b_dt, nullptr, nullptr);
    cudaStreamWaitEvent(0, ev[5], 0);

    // selective scan: cluster-16 (CPT=1) with cluster-8 (CPT=2) fallback
    {
        cudaError_t e = cudaFuncSetAttribute(
            (const void*)scan_kernel<1>,
            cudaFuncAttributeNonPortableClusterSizeAllowed, 1);
        cudaLaunchConfig_t cfg = {};
        cudaLaunchAttribute at[1];
        at[0].id = cudaLaunchAttributeClusterDimension;
        cfg.attrs = at;
        cfg.numAttrs = 1;
        cfg.blockDim = dim3(128, 1, 1);
        cfg.stream = 0;
        if (e == cudaSuccess) {
            int cs = 16;
            at[0].val.clusterDim = {16, 1, 1};
            cfg.gridDim = dim3(32, 1, 1);
            cudaLaunchKernelEx(&cfg, scan_kernel<1>, A_log, D_param, cs);
        } else {
            (void)cudaGetLastError();
            int cs = 8;
            at[0].val.clusterDim = {8, 1, 1};
            cfg.gridDim = dim3(16, 1, 1);
            cudaLaunchKernelEx(&cfg, scan_kernel<2>, A_log, D_param, cs);
        }
    }

    gate_kernel<<<(NTOK * DI / 4) / 256, 256>>>();
    cudaStreamWaitEvent(0, ev[3], 0);
    gemm_hmma<2><<<dim3(DM / 128, NTOK / 128), 256>>>(
        (const __nv_bfloat16*)p_gh, (const __nv_bfloat16*)p_woh,
        out, DM, DI, nullptr, x, r_scale);
}